// round 2
// baseline (speedup 1.0000x reference)
#include <cuda_runtime.h>
#include <math.h>

// Problem constants
#define BB 2
#define TT 2048
#define CC 1024
#define HH 16
#define HD 64
#define M_ROWS (BB*TT)        // 4096
#define QKV_N  (3*CC)         // 3072

// Scratch (no cudaMalloc allowed)
__device__ float g_qkv[(size_t)M_ROWS * QKV_N];  // [4096, 3072]
__device__ float g_y  [(size_t)M_ROWS * CC];     // [4096, 1024]

// ---------------------------------------------------------------------------
// f32x2 packed helpers (Blackwell fma.rn.f32x2: 2 fp32 FMAs per issue slot)
// ---------------------------------------------------------------------------
typedef unsigned long long u64;

__device__ __forceinline__ u64 ffma2(u64 a, u64 b, u64 c) {
    u64 d;
    asm("fma.rn.f32x2 %0, %1, %2, %3;" : "=l"(d) : "l"(a), "l"(b), "l"(c));
    return d;
}
__device__ __forceinline__ u64 pack2(float lo, float hi) {
    u64 r;
    asm("mov.b64 %0, {%1, %2};" : "=l"(r) : "f"(lo), "f"(hi));
    return r;
}
__device__ __forceinline__ float2 unpack2(u64 v) {
    float lo, hi;
    asm("mov.b64 {%0, %1}, %2;" : "=f"(lo), "=f"(hi) : "l"(v));
    return make_float2(lo, hi);
}

// ---------------------------------------------------------------------------
// SGEMM: C[M,N] = A[M,K] @ B[K,N] + bias[N]
// BM=128, BN=128, BK=8, per-thread 8x8, 256 threads.
// f32x2 inner loop + double-buffered smem + register prefetch.
// ---------------------------------------------------------------------------
#define GBM 128
#define GBN 128
#define GBK 8
#define GTM 8
#define GTN 8

__global__ __launch_bounds__(256) void sgemm_bias(
    int M, int N, int K,
    const float* __restrict__ A,
    const float* __restrict__ B,
    const float* __restrict__ bias,
    float* __restrict__ C)
{
    __shared__ u64    As[2][GBK][GBM];        // A value duplicated as (a,a): 16 KB
    __shared__ float4 Bs4[2][GBK][GBN / 4];   // 8 KB

    const int tid  = threadIdx.x;
    const int brow = blockIdx.y;
    const int bcol = blockIdx.x;

    const float* Ap = A + (size_t)brow * GBM * K;
    const float* Bp = B + (size_t)bcol * GBN;
    float*       Cp = C + (size_t)brow * GBM * N + (size_t)bcol * GBN;

    // A tile: 128x8 -> 256 float4 loads, one per thread
    const int aRow = tid >> 1;          // 0..127
    const int aCol = (tid & 1) * 4;     // 0 or 4
    // B tile: 8x128 -> 256 float4 loads
    const int bRow = tid >> 5;          // 0..7
    const int bCol = (tid & 31) * 4;    // 0..124

    const int tRow = (tid >> 4) * GTM;  // 0..120
    const int tCol = (tid & 15) * GTN;  // 0..120

    u64 acc[GTM][GTN / 2];
#pragma unroll
    for (int i = 0; i < GTM; i++)
#pragma unroll
        for (int j = 0; j < GTN / 2; j++) acc[i][j] = 0ULL;

    // prologue: load tile 0 into buffer 0
    {
        float4 a4 = *reinterpret_cast<const float4*>(Ap + (size_t)aRow * K + aCol);
        As[0][aCol + 0][aRow] = pack2(a4.x, a4.x);
        As[0][aCol + 1][aRow] = pack2(a4.y, a4.y);
        As[0][aCol + 2][aRow] = pack2(a4.z, a4.z);
        As[0][aCol + 3][aRow] = pack2(a4.w, a4.w);
        Bs4[0][bRow][bCol >> 2] =
            *reinterpret_cast<const float4*>(Bp + (size_t)bRow * N + bCol);
    }
    __syncthreads();

    const int nk = K / GBK;
    for (int kt = 0; kt < nk; kt++) {
        const int cur = kt & 1;
        const int nxt = cur ^ 1;

        // prefetch next tile (global -> registers)
        float4 a4n, b4n;
        const bool more = (kt + 1 < nk);
        if (more) {
            const int k0 = (kt + 1) * GBK;
            a4n = *reinterpret_cast<const float4*>(Ap + (size_t)aRow * K + k0 + aCol);
            b4n = *reinterpret_cast<const float4*>(Bp + (size_t)(k0 + bRow) * N + bCol);
        }

        // compute on current buffer
#pragma unroll
        for (int k = 0; k < GBK; k++) {
            u64 ra[GTM];
#pragma unroll
            for (int i = 0; i < GTM; i++) ra[i] = As[cur][k][tRow + i];
            ulonglong2 rb01 = *reinterpret_cast<const ulonglong2*>(&Bs4[cur][k][tCol >> 2]);
            ulonglong2 rb23 = *reinterpret_cast<const ulonglong2*>(&Bs4[cur][k][(tCol >> 2) + 1]);
            u64 rb[4] = {rb01.x, rb01.y, rb23.x, rb23.y};
#pragma unroll
            for (int i = 0; i < GTM; i++)
#pragma unroll
                for (int j = 0; j < GTN / 2; j++)
                    acc[i][j] = ffma2(ra[i], rb[j], acc[i][j]);
        }

        // stage next tile (registers -> other smem buffer)
        if (more) {
            As[nxt][aCol + 0][aRow] = pack2(a4n.x, a4n.x);
            As[nxt][aCol + 1][aRow] = pack2(a4n.y, a4n.y);
            As[nxt][aCol + 2][aRow] = pack2(a4n.z, a4n.z);
            As[nxt][aCol + 3][aRow] = pack2(a4n.w, a4n.w);
            Bs4[nxt][bRow][bCol >> 2] = b4n;
        }
        __syncthreads();
    }

    const float* biasp = bias + (size_t)bcol * GBN + tCol;
    float bl[GTN];
#pragma unroll
    for (int j = 0; j < GTN; j++) bl[j] = biasp[j];

#pragma unroll
    for (int i = 0; i < GTM; i++) {
#pragma unroll
        for (int j = 0; j < GTN; j += 4) {
            float2 p0 = unpack2(acc[i][(j >> 1) + 0]);
            float2 p1 = unpack2(acc[i][(j >> 1) + 1]);
            float4 v;
            v.x = p0.x + bl[j + 0];
            v.y = p0.y + bl[j + 1];
            v.z = p1.x + bl[j + 2];
            v.w = p1.y + bl[j + 3];
            *reinterpret_cast<float4*>(Cp + (size_t)(tRow + i) * N + tCol + j) = v;
        }
    }
}

// ---------------------------------------------------------------------------
// Flash attention (causal), fp32 with f32x2 packed math.
// grid: (B*H, T/128). block: 128 threads, each thread owns one q row.
// ---------------------------------------------------------------------------
#define BQ 128
#define BKV 32

__global__ __launch_bounds__(BQ) void attn_kernel(
    const float* __restrict__ qkv, float* __restrict__ y)
{
    const int bh = blockIdx.x;
    const int b  = bh / HH;
    const int h  = bh % HH;
    const int qt = blockIdx.y;
    const int tidx = threadIdx.x;
    const int qrow = qt * BQ + tidx;

    __shared__ ulonglong2 Ks2[BKV][HD / 4];   // 8 KB (pairs along d)
    __shared__ ulonglong2 Vs2[BKV][HD / 4];   // 8 KB

    const float scale = 0.125f; // 1/sqrt(64)

    // q row as 32 packed pairs, pre-scaled
    u64 q2[HD / 2];
    {
        const float* qptr = qkv + ((size_t)(b * TT + qrow)) * QKV_N + h * HD;
#pragma unroll
        for (int i = 0; i < HD / 4; i++) {
            float4 v = *reinterpret_cast<const float4*>(qptr + 4 * i);
            q2[2 * i + 0] = pack2(v.x * scale, v.y * scale);
            q2[2 * i + 1] = pack2(v.z * scale, v.w * scale);
        }
    }

    u64 o2[HD / 2];
#pragma unroll
    for (int i = 0; i < HD / 2; i++) o2[i] = 0ULL;
    float m = -1e30f, l = 0.0f;

    const float* kbase = qkv + ((size_t)b * TT) * QKV_N + CC      + h * HD;
    const float* vbase = qkv + ((size_t)b * TT) * QKV_N + 2 * CC  + h * HD;

    const int ntiles = 4 * qt + 4;  // covers k in [0, qt*128+128)

    for (int kt = 0; kt < ntiles; kt++) {
        const int kb = kt * BKV;
        __syncthreads();  // protect smem reuse from previous iteration
        // cooperative load: 32 rows x 16 float4 each for K and V
#pragma unroll
        for (int i = 0; i < 4; i++) {
            int f = tidx + BQ * i;     // 0..511
            int r = f >> 4;            // 0..31
            int c = f & 15;            // 0..15
            size_t goff = (size_t)(kb + r) * QKV_N + 4 * c;
            float4 kv = *reinterpret_cast<const float4*>(kbase + goff);
            float4 vv = *reinterpret_cast<const float4*>(vbase + goff);
            Ks2[r][c] = make_ulonglong2(pack2(kv.x, kv.y), pack2(kv.z, kv.w));
            Vs2[r][c] = make_ulonglong2(pack2(vv.x, vv.y), pack2(vv.z, vv.w));
        }
        __syncthreads();

        const bool maskTile = (kb + BKV - 1) > qrow;

        float sreg[BKV];
        float tmax = -1e30f;
#pragma unroll 4
        for (int j = 0; j < BKV; j++) {
            u64 acc = 0ULL;
#pragma unroll
            for (int c = 0; c < HD / 4; c++) {
                ulonglong2 k2 = Ks2[j][c];
                acc = ffma2(q2[2 * c + 0], k2.x, acc);
                acc = ffma2(q2[2 * c + 1], k2.y, acc);
            }
            float2 ac = unpack2(acc);
            float s = ac.x + ac.y;
            if (maskTile && (kb + j) > qrow) s = -1e30f;
            sreg[j] = s;
            tmax = fmaxf(tmax, s);
        }

        float mnew = fmaxf(m, tmax);
        float alpha = __expf(m - mnew);
        l *= alpha;
        u64 alpha2 = pack2(alpha, alpha);
        u64 zero2 = 0ULL;
#pragma unroll
        for (int d = 0; d < HD / 2; d++) o2[d] = ffma2(alpha2, o2[d], zero2);
        m = mnew;

#pragma unroll 4
        for (int j = 0; j < BKV; j++) {
            float p = __expf(sreg[j] - mnew);
            l += p;
            u64 p2 = pack2(p, p);
#pragma unroll
            for (int c = 0; c < HD / 4; c++) {
                ulonglong2 v2 = Vs2[j][c];
                o2[2 * c + 0] = ffma2(p2, v2.x, o2[2 * c + 0]);
                o2[2 * c + 1] = ffma2(p2, v2.y, o2[2 * c + 1]);
            }
        }
    }

    const float inv = 1.0f / l;
    float* yptr = y + ((size_t)(b * TT + qrow)) * CC + h * HD;
#pragma unroll
    for (int i = 0; i < HD / 4; i++) {
        float2 p0 = unpack2(o2[2 * i + 0]);
        float2 p1 = unpack2(o2[2 * i + 1]);
        float4 v;
        v.x = p0.x * inv; v.y = p0.y * inv;
        v.z = p1.x * inv; v.w = p1.y * inv;
        *reinterpret_cast<float4*>(yptr + 4 * i) = v;
    }
}

// ---------------------------------------------------------------------------
extern "C" void kernel_launch(void* const* d_in, const int* in_sizes, int n_in,
                              void* d_out, int out_size)
{
    const float* x     = (const float*)d_in[0];
    const float* w_qkv = (const float*)d_in[1];
    const float* b_qkv = (const float*)d_in[2];
    const float* w_out = (const float*)d_in[3];
    const float* b_out = (const float*)d_in[4];
    float* out = (float*)d_out;

    float* qkv_buf = nullptr;
    float* y_buf   = nullptr;
    cudaGetSymbolAddress((void**)&qkv_buf, g_qkv);
    cudaGetSymbolAddress((void**)&y_buf,   g_y);

    // 1) qkv = x @ w_qkv + b_qkv   (4096 x 3072 x 1024)
    {
        dim3 grid(QKV_N / GBN, M_ROWS / GBM);
        sgemm_bias<<<grid, 256>>>(M_ROWS, QKV_N, CC, x, w_qkv, b_qkv, qkv_buf);
    }

    // 2) flash attention -> y
    {
        dim3 grid(BB * HH, TT / BQ);
        attn_kernel<<<grid, BQ>>>(qkv_buf, y_buf);
    }

    // 3) out = y @ w_out + b_out   (4096 x 1024 x 1024)
    {
        dim3 grid(CC / GBN, M_ROWS / GBM);
        sgemm_bias<<<grid, 256>>>(M_ROWS, CC, CC, y_buf, w_out, b_out, out);
    }
}

// round 5
// speedup vs baseline: 1.5486x; 1.5486x over previous
#include <cuda_runtime.h>
#include <cuda_bf16.h>
#include <math.h>
#include <stdint.h>

// Problem constants
#define BB 2
#define TT 2048
#define CC 1024
#define HH 16
#define HD 64
#define M_ROWS (BB*TT)        // 4096
#define QKV_N  (3*CC)         // 3072
#define K3     (3*CC)         // augmented K = 3072

// ---------------------------------------------------------------------------
// Scratch (__device__ globals; no cudaMalloc allowed)
// ---------------------------------------------------------------------------
__device__ float g_qkv[(size_t)M_ROWS * QKV_N];              // fp32 QKV
__device__ float g_y  [(size_t)M_ROWS * CC];                 // fp32 attn out
__device__ __nv_bfloat16 g_xs [(size_t)M_ROWS * K3];         // x split3   [M, 3K]
__device__ __nv_bfloat16 g_ys [(size_t)M_ROWS * K3];         // y split3   [M, 3K]
__device__ __nv_bfloat16 g_wqs[(size_t)QKV_N * K3];          // w_qkv^T split3 [N=3072, 3K]
__device__ __nv_bfloat16 g_wos[(size_t)CC * K3];             // w_out^T split3 [N=1024, 3K]

// ---------------------------------------------------------------------------
// PTX helpers (sm_80+ features only: mma.sync bf16, ldmatrix, cp.async)
// ---------------------------------------------------------------------------
__device__ __forceinline__ uint32_t smem_u32(const void* p) {
    uint32_t a;
    asm("{ .reg .u64 t; cvta.to.shared.u64 t, %1; cvt.u32.u64 %0, t; }" : "=r"(a) : "l"(p));
    return a;
}
__device__ __forceinline__ void cp16(uint32_t dst, const void* src) {
    asm volatile("cp.async.cg.shared.global [%0], [%1], 16;" :: "r"(dst), "l"(src));
}
#define CP_COMMIT() asm volatile("cp.async.commit_group;" ::: "memory")
#define CP_WAIT(n)  asm volatile("cp.async.wait_group %0;" :: "n"(n) : "memory")

__device__ __forceinline__ void ldsm4(uint32_t* r, uint32_t addr) {
    asm volatile("ldmatrix.sync.aligned.m8n8.x4.shared.b16 {%0,%1,%2,%3}, [%4];"
        : "=r"(r[0]), "=r"(r[1]), "=r"(r[2]), "=r"(r[3]) : "r"(addr));
}
__device__ __forceinline__ void mma16816(float* d, const uint32_t* a, const uint32_t* b) {
    asm volatile(
        "mma.sync.aligned.m16n8k16.row.col.f32.bf16.bf16.f32 "
        "{%0,%1,%2,%3}, {%4,%5,%6,%7}, {%8,%9}, {%0,%1,%2,%3};"
        : "+f"(d[0]), "+f"(d[1]), "+f"(d[2]), "+f"(d[3])
        : "r"(a[0]), "r"(a[1]), "r"(a[2]), "r"(a[3]), "r"(b[0]), "r"(b[1]));
}

// ---------------------------------------------------------------------------
// Conversion kernels (split-bf16 via K-concatenation)
// A' = [ah | ah | al], B' = [bh | bl | bh] so dot(A',B') = ah*bh + ah*bl + al*bh
// ---------------------------------------------------------------------------
__global__ void split3_act(const float* __restrict__ in,
                           __nv_bfloat16* __restrict__ out, int n4)
{
    int i = blockIdx.x * blockDim.x + threadIdx.x;
    if (i >= n4) return;
    int m  = i >> 8;            // CC/4 = 256 float4 per row
    int kc = i & 255;
    float4 v = reinterpret_cast<const float4*>(in)[i];
    __nv_bfloat16 h[4], l[4];
    float f[4] = {v.x, v.y, v.z, v.w};
#pragma unroll
    for (int j = 0; j < 4; j++) {
        h[j] = __float2bfloat16(f[j]);
        l[j] = __float2bfloat16(f[j] - __bfloat162float(h[j]));
    }
    __nv_bfloat162 hp0(h[0], h[1]), hp1(h[2], h[3]);
    __nv_bfloat162 lp0(l[0], l[1]), lp1(l[2], l[3]);
    __nv_bfloat162* o = reinterpret_cast<__nv_bfloat162*>(out + (size_t)m * K3 + kc * 4);
    o[0] = hp0; o[1] = hp1;                                   // seg0: ah
    o[CC / 2 + 0] = hp0; o[CC / 2 + 1] = hp1;                 // seg1: ah
    o[CC + 0] = lp0; o[CC + 1] = lp1;                         // seg2: al
}

// W [K=1024, N] fp32 row-major -> out [N, 3K] bf16: [bh | bl | bh]
__global__ __launch_bounds__(256) void tsplit3(
    const float* __restrict__ W, int N, __nv_bfloat16* __restrict__ out)
{
    __shared__ float t[32][33];
    const int nb = blockIdx.x * 32;
    const int kb = blockIdx.y * 32;
    const int tx = threadIdx.x & 31;
    const int ty = threadIdx.x >> 5;  // 0..7
    for (int r = ty; r < 32; r += 8)
        t[r][tx] = W[(size_t)(kb + r) * N + nb + tx];
    __syncthreads();
    for (int r = ty; r < 32; r += 8) {
        float v = t[tx][r];
        __nv_bfloat16 h = __float2bfloat16(v);
        __nv_bfloat16 l = __float2bfloat16(v - __bfloat162float(h));
        size_t o = (size_t)(nb + r) * K3 + kb + tx;
        out[o]          = h;   // seg0: bh
        out[o + CC]     = l;   // seg1: bl
        out[o + 2 * CC] = h;   // seg2: bh
    }
}

// ---------------------------------------------------------------------------
// bf16 HMMA GEMM: C[M,N] = A'[M,3K] @ B'[N,3K]^T + bias[N]
// 128x128 block tile, BK=32, 8 warps (2x4), warp tile 64x32.
// smem rows padded to 80B (conflict-free ldmatrix), cp.async double-buffered.
// ---------------------------------------------------------------------------
#define PITCH 80
#define ATILE (128 * PITCH)   // 10240 B
#define STAGE (2 * ATILE)     // A + B
#define NKB   (K3 / 32)       // 96

__global__ __launch_bounds__(256) void gemm_mma(
    int N,
    const __nv_bfloat16* __restrict__ A,
    const __nv_bfloat16* __restrict__ B,
    const float* __restrict__ bias,
    float* __restrict__ C)
{
    __shared__ char smem[2 * STAGE];   // 40960 B
    const uint32_t sbase = smem_u32(smem);

    const int tid  = threadIdx.x;
    const int lane = tid & 31;
    const int wid  = tid >> 5;
    const int wm   = wid >> 2;         // 0..1
    const int wn   = wid & 3;          // 0..3
    const int m0   = blockIdx.y * 128;
    const int n0   = blockIdx.x * 128;

    // cp.async chunk mapping: 1024 x 16B chunks per stage (A 512 + B 512)
    const int arow = tid >> 1;               // for j in {0,1}: rows tid>>1... recompute below
    (void)arow;

    float acc[4][4][4];
#pragma unroll
    for (int mi = 0; mi < 4; mi++)
#pragma unroll
        for (int nj = 0; nj < 4; nj++)
#pragma unroll
            for (int r = 0; r < 4; r++) acc[mi][nj][r] = 0.0f;

    auto load_stage = [&](int kb, int st) {
        const uint32_t sa = sbase + st * STAGE;
        const uint32_t sb = sa + ATILE;
        const int k0 = kb * 32;
#pragma unroll
        for (int j = 0; j < 2; j++) {
            int id = tid + 256 * j;          // 0..511
            int r = id >> 2;                 // 0..127
            int c = id & 3;                  // 0..3
            cp16(sa + r * PITCH + c * 16,
                 A + (size_t)(m0 + r) * K3 + k0 + c * 8);
        }
#pragma unroll
        for (int j = 0; j < 2; j++) {
            int id = tid + 256 * j;
            int r = id >> 2;
            int c = id & 3;
            cp16(sb + r * PITCH + c * 16,
                 B + (size_t)(n0 + r) * K3 + k0 + c * 8);
        }
        CP_COMMIT();
    };

    load_stage(0, 0);

    for (int kb = 0; kb < NKB; kb++) {
        const int st = kb & 1;
        if (kb + 1 < NKB) load_stage(kb + 1, st ^ 1);

        if (kb + 1 < NKB) { CP_WAIT(1); } else { CP_WAIT(0); }
        __syncthreads();

        const uint32_t sa = sbase + st * STAGE;
        const uint32_t sb = sa + ATILE;

#pragma unroll
        for (int ks = 0; ks < 2; ks++) {
            uint32_t af[4][4];
#pragma unroll
            for (int mi = 0; mi < 4; mi++) {
                uint32_t addr = sa + (wm * 64 + mi * 16 + (lane & 15)) * PITCH
                              + ((lane >> 4) * 16) + ks * 32;
                ldsm4(af[mi], addr);
            }
            uint32_t bf[2][4];
#pragma unroll
            for (int nj2 = 0; nj2 < 2; nj2++) {
                int nrow = wn * 32 + nj2 * 16 + (lane & 7) + (((lane >> 4) & 1) * 8);
                uint32_t addr = sb + nrow * PITCH + ks * 32 + (((lane >> 3) & 1) * 16);
                ldsm4(bf[nj2], addr);
            }
#pragma unroll
            for (int mi = 0; mi < 4; mi++)
#pragma unroll
                for (int nj = 0; nj < 4; nj++)
                    mma16816(acc[mi][nj], af[mi], &bf[nj >> 1][(nj & 1) * 2]);
        }
        __syncthreads();
    }

    // Epilogue: write fp32 + bias
#pragma unroll
    for (int mi = 0; mi < 4; mi++) {
#pragma unroll
        for (int nj = 0; nj < 4; nj++) {
            int row = m0 + wm * 64 + mi * 16 + (lane >> 2);
            int col = n0 + wn * 32 + nj * 8 + 2 * (lane & 3);
            float2 bz = *reinterpret_cast<const float2*>(bias + col);
            float2 v0 = make_float2(acc[mi][nj][0] + bz.x, acc[mi][nj][1] + bz.y);
            float2 v1 = make_float2(acc[mi][nj][2] + bz.x, acc[mi][nj][3] + bz.y);
            *reinterpret_cast<float2*>(C + (size_t)row * N + col) = v0;
            *reinterpret_cast<float2*>(C + (size_t)(row + 8) * N + col) = v1;
        }
    }
}

// ---------------------------------------------------------------------------
// Flash attention (causal), fp32 (R1 version)
// ---------------------------------------------------------------------------
#define BQ 128
#define BKV 32

__global__ __launch_bounds__(BQ) void attn_kernel(
    const float* __restrict__ qkv, float* __restrict__ y)
{
    const int bh = blockIdx.x;
    const int b  = bh / HH;
    const int h  = bh % HH;
    const int qt = blockIdx.y;
    const int tidx = threadIdx.x;
    const int qrow = qt * BQ + tidx;

    __shared__ float4 Ks[BKV][HD / 4];
    __shared__ float4 Vs[BKV][HD / 4];

    const float scale = 0.125f;

    float4 q4[HD / 4];
    {
        const float* qptr = qkv + ((size_t)(b * TT + qrow)) * QKV_N + h * HD;
#pragma unroll
        for (int i = 0; i < HD / 4; i++) {
            float4 v = *reinterpret_cast<const float4*>(qptr + 4 * i);
            v.x *= scale; v.y *= scale; v.z *= scale; v.w *= scale;
            q4[i] = v;
        }
    }

    float4 o4[HD / 4];
#pragma unroll
    for (int i = 0; i < HD / 4; i++) o4[i] = make_float4(0.f, 0.f, 0.f, 0.f);
    float m = -1e30f, l = 0.0f;

    const float* kbase = qkv + ((size_t)b * TT) * QKV_N + CC      + h * HD;
    const float* vbase = qkv + ((size_t)b * TT) * QKV_N + 2 * CC  + h * HD;

    const int ntiles = 4 * qt + 4;

    for (int kt = 0; kt < ntiles; kt++) {
        const int kb = kt * BKV;
        __syncthreads();
#pragma unroll
        for (int i = 0; i < 4; i++) {
            int f = tidx + BQ * i;
            int r = f >> 4;
            int c = f & 15;
            size_t goff = (size_t)(kb + r) * QKV_N + 4 * c;
            Ks[r][c] = *reinterpret_cast<const float4*>(kbase + goff);
            Vs[r][c] = *reinterpret_cast<const float4*>(vbase + goff);
        }
        __syncthreads();

        const bool maskTile = (kb + BKV - 1) > qrow;

        float sreg[BKV];
        float tmax = -1e30f;
#pragma unroll 4
        for (int j = 0; j < BKV; j++) {
            float s = 0.0f;
#pragma unroll
            for (int d = 0; d < HD / 4; d++) {
                float4 kv = Ks[j][d];
                s = fmaf(q4[d].x, kv.x, s);
                s = fmaf(q4[d].y, kv.y, s);
                s = fmaf(q4[d].z, kv.z, s);
                s = fmaf(q4[d].w, kv.w, s);
            }
            if (maskTile && (kb + j) > qrow) s = -1e30f;
            sreg[j] = s;
            tmax = fmaxf(tmax, s);
        }

        float mnew = fmaxf(m, tmax);
        float alpha = __expf(m - mnew);
        l *= alpha;
#pragma unroll
        for (int d = 0; d < HD / 4; d++) {
            o4[d].x *= alpha; o4[d].y *= alpha;
            o4[d].z *= alpha; o4[d].w *= alpha;
        }
        m = mnew;

#pragma unroll 4
        for (int j = 0; j < BKV; j++) {
            float p = __expf(sreg[j] - mnew);
            l += p;
#pragma unroll
            for (int d = 0; d < HD / 4; d++) {
                float4 vv = Vs[j][d];
                o4[d].x = fmaf(p, vv.x, o4[d].x);
                o4[d].y = fmaf(p, vv.y, o4[d].y);
                o4[d].z = fmaf(p, vv.z, o4[d].z);
                o4[d].w = fmaf(p, vv.w, o4[d].w);
            }
        }
    }

    const float inv = 1.0f / l;
    float* yptr = y + ((size_t)(b * TT + qrow)) * CC + h * HD;
#pragma unroll
    for (int i = 0; i < HD / 4; i++) {
        float4 v = o4[i];
        v.x *= inv; v.y *= inv; v.z *= inv; v.w *= inv;
        *reinterpret_cast<float4*>(yptr + 4 * i) = v;
    }
}

// ---------------------------------------------------------------------------
extern "C" void kernel_launch(void* const* d_in, const int* in_sizes, int n_in,
                              void* d_out, int out_size)
{
    const float* x     = (const float*)d_in[0];
    const float* w_qkv = (const float*)d_in[1];
    const float* b_qkv = (const float*)d_in[2];
    const float* w_out = (const float*)d_in[3];
    const float* b_out = (const float*)d_in[4];
    float* out = (float*)d_out;

    float* qkv_buf = nullptr;  cudaGetSymbolAddress((void**)&qkv_buf, g_qkv);
    float* y_buf   = nullptr;  cudaGetSymbolAddress((void**)&y_buf,   g_y);
    __nv_bfloat16 *xs, *ys, *wqs, *wos;
    cudaGetSymbolAddress((void**)&xs,  g_xs);
    cudaGetSymbolAddress((void**)&ys,  g_ys);
    cudaGetSymbolAddress((void**)&wqs, g_wqs);
    cudaGetSymbolAddress((void**)&wos, g_wos);

    // Conversions
    {
        int n4 = M_ROWS * CC / 4;
        split3_act<<<(n4 + 255) / 256, 256>>>(x, xs, n4);
        dim3 g1(QKV_N / 32, CC / 32);
        tsplit3<<<g1, 256>>>(w_qkv, QKV_N, wqs);
        dim3 g2(CC / 32, CC / 32);
        tsplit3<<<g2, 256>>>(w_out, CC, wos);
    }

    // 1) qkv = x @ w_qkv + b_qkv  (bf16 HMMA, K'=3072)
    {
        dim3 grid(QKV_N / 128, M_ROWS / 128);
        gemm_mma<<<grid, 256>>>(QKV_N, xs, wqs, b_qkv, qkv_buf);
    }

    // 2) flash attention -> y (fp32)
    {
        dim3 grid(BB * HH, TT / BQ);
        attn_kernel<<<grid, BQ>>>(qkv_buf, y_buf);
    }

    // 3) split y, then out = y @ w_out + b_out
    {
        int n4 = M_ROWS * CC / 4;
        split3_act<<<(n4 + 255) / 256, 256>>>(y_buf, ys, n4);
        dim3 grid(CC / 128, M_ROWS / 128);
        gemm_mma<<<grid, 256>>>(CC, ys, wos, b_out, out);
    }
}

// round 6
// speedup vs baseline: 3.0868x; 1.9933x over previous
#include <cuda_runtime.h>
#include <cuda_bf16.h>
#include <math.h>
#include <stdint.h>

// Problem constants
#define BB 2
#define TT 2048
#define CC 1024
#define HH 16
#define HD 64
#define M_ROWS (BB*TT)        // 4096
#define QKV_N  (3*CC)         // 3072
#define K3     (3*CC)         // augmented K = 3072

// ---------------------------------------------------------------------------
// Scratch (__device__ globals; no cudaMalloc allowed)
// ---------------------------------------------------------------------------
__device__ float g_qkv[(size_t)M_ROWS * QKV_N];              // fp32 QKV
__device__ float g_y  [(size_t)M_ROWS * CC];                 // fp32 attn out
__device__ __nv_bfloat16 g_xs [(size_t)M_ROWS * K3];         // x split3   [M, 3K]
__device__ __nv_bfloat16 g_ys [(size_t)M_ROWS * K3];         // y split3   [M, 3K]
__device__ __nv_bfloat16 g_wqs[(size_t)QKV_N * K3];          // w_qkv^T split3
__device__ __nv_bfloat16 g_wos[(size_t)CC * K3];             // w_out^T split3
// head-major attention operands [B*H, T, 64]
#define HSZ ((size_t)BB * HH * TT * HD)
__device__ __nv_bfloat16 g_qh[HSZ];
__device__ __nv_bfloat16 g_ql[HSZ];
__device__ __nv_bfloat16 g_kh[HSZ];
__device__ __nv_bfloat16 g_kl[HSZ];
__device__ __nv_bfloat16 g_vh[HSZ];
__device__ __nv_bfloat16 g_vl[HSZ];

// ---------------------------------------------------------------------------
// PTX helpers (sm_80+ baseline: mma.sync bf16, ldmatrix, cp.async)
// ---------------------------------------------------------------------------
__device__ __forceinline__ uint32_t smem_u32(const void* p) {
    uint32_t a;
    asm("{ .reg .u64 t; cvta.to.shared.u64 t, %1; cvt.u32.u64 %0, t; }" : "=r"(a) : "l"(p));
    return a;
}
__device__ __forceinline__ void cp16(uint32_t dst, const void* src) {
    asm volatile("cp.async.cg.shared.global [%0], [%1], 16;" :: "r"(dst), "l"(src));
}
#define CP_COMMIT() asm volatile("cp.async.commit_group;" ::: "memory")
#define CP_WAIT(n)  asm volatile("cp.async.wait_group %0;" :: "n"(n) : "memory")

__device__ __forceinline__ void ldsm4(uint32_t* r, uint32_t addr) {
    asm volatile("ldmatrix.sync.aligned.m8n8.x4.shared.b16 {%0,%1,%2,%3}, [%4];"
        : "=r"(r[0]), "=r"(r[1]), "=r"(r[2]), "=r"(r[3]) : "r"(addr));
}
__device__ __forceinline__ void ldsm4t(uint32_t* r, uint32_t addr) {
    asm volatile("ldmatrix.sync.aligned.m8n8.x4.trans.shared.b16 {%0,%1,%2,%3}, [%4];"
        : "=r"(r[0]), "=r"(r[1]), "=r"(r[2]), "=r"(r[3]) : "r"(addr));
}
__device__ __forceinline__ void mma16816(float* d, const uint32_t* a, const uint32_t* b) {
    asm volatile(
        "mma.sync.aligned.m16n8k16.row.col.f32.bf16.bf16.f32 "
        "{%0,%1,%2,%3}, {%4,%5,%6,%7}, {%8,%9}, {%0,%1,%2,%3};"
        : "+f"(d[0]), "+f"(d[1]), "+f"(d[2]), "+f"(d[3])
        : "r"(a[0]), "r"(a[1]), "r"(a[2]), "r"(a[3]), "r"(b[0]), "r"(b[1]));
}
__device__ __forceinline__ uint32_t pack_bf16x2(__nv_bfloat16 a, __nv_bfloat16 b) {
    __nv_bfloat162 h = __halves2bfloat162(a, b);
    return *reinterpret_cast<uint32_t*>(&h);
}

// ---------------------------------------------------------------------------
// Conversion kernels for the GEMMs (unchanged from R5)
// ---------------------------------------------------------------------------
__global__ void split3_act(const float* __restrict__ in,
                           __nv_bfloat16* __restrict__ out, int n4)
{
    int i = blockIdx.x * blockDim.x + threadIdx.x;
    if (i >= n4) return;
    int m  = i >> 8;
    int kc = i & 255;
    float4 v = reinterpret_cast<const float4*>(in)[i];
    __nv_bfloat16 h[4], l[4];
    float f[4] = {v.x, v.y, v.z, v.w};
#pragma unroll
    for (int j = 0; j < 4; j++) {
        h[j] = __float2bfloat16(f[j]);
        l[j] = __float2bfloat16(f[j] - __bfloat162float(h[j]));
    }
    __nv_bfloat162 hp0(h[0], h[1]), hp1(h[2], h[3]);
    __nv_bfloat162 lp0(l[0], l[1]), lp1(l[2], l[3]);
    __nv_bfloat162* o = reinterpret_cast<__nv_bfloat162*>(out + (size_t)m * K3 + kc * 4);
    o[0] = hp0; o[1] = hp1;
    o[CC / 2 + 0] = hp0; o[CC / 2 + 1] = hp1;
    o[CC + 0] = lp0; o[CC + 1] = lp1;
}

__global__ __launch_bounds__(256) void tsplit3(
    const float* __restrict__ W, int N, __nv_bfloat16* __restrict__ out)
{
    __shared__ float t[32][33];
    const int nb = blockIdx.x * 32;
    const int kb = blockIdx.y * 32;
    const int tx = threadIdx.x & 31;
    const int ty = threadIdx.x >> 5;
    for (int r = ty; r < 32; r += 8)
        t[r][tx] = W[(size_t)(kb + r) * N + nb + tx];
    __syncthreads();
    for (int r = ty; r < 32; r += 8) {
        float v = t[tx][r];
        __nv_bfloat16 h = __float2bfloat16(v);
        __nv_bfloat16 l = __float2bfloat16(v - __bfloat162float(h));
        size_t o = (size_t)(nb + r) * K3 + kb + tx;
        out[o]          = h;
        out[o + CC]     = l;
        out[o + 2 * CC] = h;
    }
}

// split qkv (fp32, [M, 3C]) into head-major hi/lo bf16 buffers; Q pre-scaled 1/8
__global__ void split6(const float* __restrict__ qkv,
                       __nv_bfloat16* __restrict__ qh, __nv_bfloat16* __restrict__ ql,
                       __nv_bfloat16* __restrict__ kh, __nv_bfloat16* __restrict__ kl,
                       __nv_bfloat16* __restrict__ vh, __nv_bfloat16* __restrict__ vl)
{
    int i = blockIdx.x * blockDim.x + threadIdx.x;   // over M_ROWS * 768
    if (i >= M_ROWS * 768) return;
    int m = i / 768, c4 = i % 768;
    int col = c4 * 4;
    int seg = col >> 10;
    int hc = col & 1023;
    int h = hc >> 6, d = hc & 63;
    int b = m >> 11, t = m & 2047;
    float4 v = *reinterpret_cast<const float4*>(qkv + (size_t)m * QKV_N + col);
    if (seg == 0) { v.x *= 0.125f; v.y *= 0.125f; v.z *= 0.125f; v.w *= 0.125f; }
    float f[4] = {v.x, v.y, v.z, v.w};
    __nv_bfloat16 hh[4];
    __nv_bfloat16 ll[4];
#pragma unroll
    for (int j = 0; j < 4; j++) {
        hh[j] = __float2bfloat16(f[j]);
        ll[j] = __float2bfloat16(f[j] - __bfloat162float(hh[j]));
    }
    size_t dst = (((size_t)(b * HH + h)) * TT + t) * HD + d;
    __nv_bfloat16* hp = (seg == 0) ? qh : (seg == 1) ? kh : vh;
    __nv_bfloat16* lp = (seg == 0) ? ql : (seg == 1) ? kl : vl;
    uint2 hv = make_uint2(pack_bf16x2(hh[0], hh[1]), pack_bf16x2(hh[2], hh[3]));
    uint2 lv = make_uint2(pack_bf16x2(ll[0], ll[1]), pack_bf16x2(ll[2], ll[3]));
    *reinterpret_cast<uint2*>(hp + dst) = hv;
    *reinterpret_cast<uint2*>(lp + dst) = lv;
}

// ---------------------------------------------------------------------------
// bf16 HMMA GEMM (from R5): C[M,N] = A'[M,3K] @ B'[N,3K]^T + bias[N]
// ---------------------------------------------------------------------------
#define PITCH 80
#define ATILE (128 * PITCH)
#define STAGE (2 * ATILE)
#define NKB   (K3 / 32)

__global__ __launch_bounds__(256) void gemm_mma(
    int N,
    const __nv_bfloat16* __restrict__ A,
    const __nv_bfloat16* __restrict__ B,
    const float* __restrict__ bias,
    float* __restrict__ C)
{
    __shared__ char smem[2 * STAGE];
    const uint32_t sbase = smem_u32(smem);

    const int tid  = threadIdx.x;
    const int lane = tid & 31;
    const int wid  = tid >> 5;
    const int wm   = wid >> 2;
    const int wn   = wid & 3;
    const int m0   = blockIdx.y * 128;
    const int n0   = blockIdx.x * 128;

    float acc[4][4][4];
#pragma unroll
    for (int mi = 0; mi < 4; mi++)
#pragma unroll
        for (int nj = 0; nj < 4; nj++)
#pragma unroll
            for (int r = 0; r < 4; r++) acc[mi][nj][r] = 0.0f;

    auto load_stage = [&](int kb, int st) {
        const uint32_t sa = sbase + st * STAGE;
        const uint32_t sb = sa + ATILE;
        const int k0 = kb * 32;
#pragma unroll
        for (int j = 0; j < 2; j++) {
            int id = tid + 256 * j;
            int r = id >> 2;
            int c = id & 3;
            cp16(sa + r * PITCH + c * 16, A + (size_t)(m0 + r) * K3 + k0 + c * 8);
        }
#pragma unroll
        for (int j = 0; j < 2; j++) {
            int id = tid + 256 * j;
            int r = id >> 2;
            int c = id & 3;
            cp16(sb + r * PITCH + c * 16, B + (size_t)(n0 + r) * K3 + k0 + c * 8);
        }
        CP_COMMIT();
    };

    load_stage(0, 0);

    for (int kb = 0; kb < NKB; kb++) {
        const int st = kb & 1;
        if (kb + 1 < NKB) load_stage(kb + 1, st ^ 1);
        if (kb + 1 < NKB) { CP_WAIT(1); } else { CP_WAIT(0); }
        __syncthreads();

        const uint32_t sa = sbase + st * STAGE;
        const uint32_t sb = sa + ATILE;

#pragma unroll
        for (int ks = 0; ks < 2; ks++) {
            uint32_t af[4][4];
#pragma unroll
            for (int mi = 0; mi < 4; mi++) {
                uint32_t addr = sa + (wm * 64 + mi * 16 + (lane & 15)) * PITCH
                              + ((lane >> 4) * 16) + ks * 32;
                ldsm4(af[mi], addr);
            }
            uint32_t bf[2][4];
#pragma unroll
            for (int nj2 = 0; nj2 < 2; nj2++) {
                int nrow = wn * 32 + nj2 * 16 + (lane & 7) + (((lane >> 4) & 1) * 8);
                uint32_t addr = sb + nrow * PITCH + ks * 32 + (((lane >> 3) & 1) * 16);
                ldsm4(bf[nj2], addr);
            }
#pragma unroll
            for (int mi = 0; mi < 4; mi++)
#pragma unroll
                for (int nj = 0; nj < 4; nj++)
                    mma16816(acc[mi][nj], af[mi], &bf[nj >> 1][(nj & 1) * 2]);
        }
        __syncthreads();
    }

#pragma unroll
    for (int mi = 0; mi < 4; mi++) {
#pragma unroll
        for (int nj = 0; nj < 4; nj++) {
            int row = m0 + wm * 64 + mi * 16 + (lane >> 2);
            int col = n0 + wn * 32 + nj * 8 + 2 * (lane & 3);
            float2 bz = *reinterpret_cast<const float2*>(bias + col);
            float2 v0 = make_float2(acc[mi][nj][0] + bz.x, acc[mi][nj][1] + bz.y);
            float2 v1 = make_float2(acc[mi][nj][2] + bz.x, acc[mi][nj][3] + bz.y);
            *reinterpret_cast<float2*>(C + (size_t)row * N + col) = v0;
            *reinterpret_cast<float2*>(C + (size_t)(row + 8) * N + col) = v1;
        }
    }
}

// ---------------------------------------------------------------------------
// Flash attention on HMMA, split-bf16 precision (3-term) for QK and PV.
// Block: 128 threads (4 warps). Q tile 64 rows (16/warp), KV tiles of 64.
// smem: Qh,Ql (loaded once) + double-buffered Kh,Kl,Vh,Vl. Pitch 144B.
// ---------------------------------------------------------------------------
#define AP 144
#define ATILE_B (64 * AP)            // 9216
#define Q_H 0
#define Q_L ATILE_B
#define STG (2 * ATILE_B)            // 18432
#define KV_STAGE (4 * ATILE_B)       // 36864
#define ATTN_SMEM (STG + 2 * KV_STAGE)  // 92160
#define NQT (TT / 64)                // 32

__global__ __launch_bounds__(128) void attn_mma(
    const __nv_bfloat16* __restrict__ Qh, const __nv_bfloat16* __restrict__ Ql,
    const __nv_bfloat16* __restrict__ Kh, const __nv_bfloat16* __restrict__ Kl,
    const __nv_bfloat16* __restrict__ Vh, const __nv_bfloat16* __restrict__ Vl,
    float* __restrict__ y)
{
    extern __shared__ char sm[];
    const uint32_t sb = smem_u32(sm);
    const int tid  = threadIdx.x;
    const int lane = tid & 31;
    const int wq   = tid >> 5;
    const int bx   = blockIdx.x;
    const int qi   = (NQT - 1) - (bx >> 5);    // heavy tiles first
    const int bh   = bx & 31;
    const int b    = bh >> 4;
    const int h    = bh & 15;
    const size_t hoff = (size_t)bh * TT * HD;

    // Q tiles: 64 rows x 128B, hi+lo
#pragma unroll
    for (int j = 0; j < 4; j++) {
        int id = tid + 128 * j;   // 0..511
        int r = id >> 3, c = id & 7;
        const size_t g = hoff + (size_t)(qi * 64 + r) * HD + c * 8;
        cp16(sb + Q_H + r * AP + c * 16, Qh + g);
        cp16(sb + Q_L + r * AP + c * 16, Ql + g);
    }
    CP_COMMIT();

    auto load_kv = [&](int kt, int st) {
        const uint32_t s0 = sb + STG + st * KV_STAGE;
        const int t0 = kt * 64;
#pragma unroll
        for (int j = 0; j < 4; j++) {
            int id = tid + 128 * j;
            int r = id >> 3, c = id & 7;
            const size_t g = hoff + (size_t)(t0 + r) * HD + c * 8;
            const uint32_t so = r * AP + c * 16;
            cp16(s0 + 0 * ATILE_B + so, Kh + g);
            cp16(s0 + 1 * ATILE_B + so, Kl + g);
            cp16(s0 + 2 * ATILE_B + so, Vh + g);
            cp16(s0 + 3 * ATILE_B + so, Vl + g);
        }
        CP_COMMIT();
    };

    load_kv(0, 0);
    CP_WAIT(0);
    __syncthreads();

    // Q fragments (register resident): 4 k-steps x 4 regs, hi+lo
    uint32_t qhf[4][4], qlf[4][4];
#pragma unroll
    for (int ks = 0; ks < 4; ks++) {
        uint32_t ao = (wq * 16 + (lane & 15)) * AP + (ks * 16 + (lane >> 4) * 8) * 2;
        ldsm4(qhf[ks], sb + Q_H + ao);
        ldsm4(qlf[ks], sb + Q_L + ao);
    }

    float oacc[8][4];
#pragma unroll
    for (int j = 0; j < 8; j++)
#pragma unroll
        for (int r = 0; r < 4; r++) oacc[j][r] = 0.0f;
    float m_a = -1e30f, m_b = -1e30f, l_a = 0.0f, l_b = 0.0f;

    for (int kt = 0; kt <= qi; kt++) {
        const int st = kt & 1;
        if (kt < qi) load_kv(kt + 1, st ^ 1);

        const uint32_t s0 = sb + STG + st * KV_STAGE;

        // ---- S = Q K^T (3-term split) ----
        float sacc[8][4];
#pragma unroll
        for (int j = 0; j < 8; j++)
#pragma unroll
            for (int r = 0; r < 4; r++) sacc[j][r] = 0.0f;

#pragma unroll
        for (int ks = 0; ks < 4; ks++) {
#pragma unroll
            for (int jp = 0; jp < 4; jp++) {
                uint32_t ro = ((2 * jp + ((lane >> 4) & 1)) * 8 + (lane & 7)) * AP
                            + (ks * 16 + ((lane >> 3) & 1) * 8) * 2;
                uint32_t kbh[4], kbl[4];
                ldsm4(kbh, s0 + 0 * ATILE_B + ro);
                ldsm4(kbl, s0 + 1 * ATILE_B + ro);
                mma16816(sacc[2 * jp],     qhf[ks], &kbh[0]);
                mma16816(sacc[2 * jp],     qlf[ks], &kbh[0]);
                mma16816(sacc[2 * jp],     qhf[ks], &kbl[0]);
                mma16816(sacc[2 * jp + 1], qhf[ks], &kbh[2]);
                mma16816(sacc[2 * jp + 1], qlf[ks], &kbh[2]);
                mma16816(sacc[2 * jp + 1], qhf[ks], &kbl[2]);
            }
        }

        // ---- causal mask on diagonal tile ----
        if (kt == qi) {
            const int rA = wq * 16 + (lane >> 2);
            const int rB = rA + 8;
#pragma unroll
            for (int j = 0; j < 8; j++) {
                const int cl = j * 8 + 2 * (lane & 3);
                if (cl     > rA) sacc[j][0] = -1e30f;
                if (cl + 1 > rA) sacc[j][1] = -1e30f;
                if (cl     > rB) sacc[j][2] = -1e30f;
                if (cl + 1 > rB) sacc[j][3] = -1e30f;
            }
        }

        // ---- online softmax ----
        float mx_a = -1e30f, mx_b = -1e30f;
#pragma unroll
        for (int j = 0; j < 8; j++) {
            mx_a = fmaxf(mx_a, fmaxf(sacc[j][0], sacc[j][1]));
            mx_b = fmaxf(mx_b, fmaxf(sacc[j][2], sacc[j][3]));
        }
        mx_a = fmaxf(mx_a, __shfl_xor_sync(0xffffffff, mx_a, 1));
        mx_a = fmaxf(mx_a, __shfl_xor_sync(0xffffffff, mx_a, 2));
        mx_b = fmaxf(mx_b, __shfl_xor_sync(0xffffffff, mx_b, 1));
        mx_b = fmaxf(mx_b, __shfl_xor_sync(0xffffffff, mx_b, 2));

        const float mn_a = fmaxf(m_a, mx_a);
        const float mn_b = fmaxf(m_b, mx_b);
        const float al_a = __expf(m_a - mn_a);
        const float al_b = __expf(m_b - mn_b);
        l_a *= al_a; l_b *= al_b;
        m_a = mn_a;  m_b = mn_b;
#pragma unroll
        for (int j = 0; j < 8; j++) {
            oacc[j][0] *= al_a; oacc[j][1] *= al_a;
            oacc[j][2] *= al_b; oacc[j][3] *= al_b;
        }

        uint32_t pha[8], phb[8], pla[8], plb[8];
#pragma unroll
        for (int j = 0; j < 8; j++) {
            float p0 = __expf(sacc[j][0] - mn_a);
            float p1 = __expf(sacc[j][1] - mn_a);
            float p2 = __expf(sacc[j][2] - mn_b);
            float p3 = __expf(sacc[j][3] - mn_b);
            l_a += p0 + p1;
            l_b += p2 + p3;
            __nv_bfloat16 h0 = __float2bfloat16(p0), h1 = __float2bfloat16(p1);
            __nv_bfloat16 h2 = __float2bfloat16(p2), h3 = __float2bfloat16(p3);
            pha[j] = pack_bf16x2(h0, h1);
            phb[j] = pack_bf16x2(h2, h3);
            pla[j] = pack_bf16x2(__float2bfloat16(p0 - __bfloat162float(h0)),
                                 __float2bfloat16(p1 - __bfloat162float(h1)));
            plb[j] = pack_bf16x2(__float2bfloat16(p2 - __bfloat162float(h2)),
                                 __float2bfloat16(p3 - __bfloat162float(h3)));
        }

        // ---- O += P V (3-term split) ----
#pragma unroll
        for (int ks = 0; ks < 4; ks++) {
            uint32_t Ah[4] = {pha[2 * ks], phb[2 * ks], pha[2 * ks + 1], phb[2 * ks + 1]};
            uint32_t Al[4] = {pla[2 * ks], plb[2 * ks], pla[2 * ks + 1], plb[2 * ks + 1]};
#pragma unroll
            for (int dp = 0; dp < 4; dp++) {
                uint32_t vo = (ks * 16 + (lane & 15)) * AP
                            + (dp * 16 + ((lane >> 4) & 1) * 8) * 2;
                uint32_t vbh[4], vbl[4];
                ldsm4t(vbh, s0 + 2 * ATILE_B + vo);
                ldsm4t(vbl, s0 + 3 * ATILE_B + vo);
                mma16816(oacc[2 * dp],     Ah, &vbh[0]);
                mma16816(oacc[2 * dp],     Al, &vbh[0]);
                mma16816(oacc[2 * dp],     Ah, &vbl[0]);
                mma16816(oacc[2 * dp + 1], Ah, &vbh[2]);
                mma16816(oacc[2 * dp + 1], Al, &vbh[2]);
                mma16816(oacc[2 * dp + 1], Ah, &vbl[2]);
            }
        }

        if (kt < qi) { CP_WAIT(0); }
        __syncthreads();
    }

    // ---- finalize ----
    l_a += __shfl_xor_sync(0xffffffff, l_a, 1);
    l_a += __shfl_xor_sync(0xffffffff, l_a, 2);
    l_b += __shfl_xor_sync(0xffffffff, l_b, 1);
    l_b += __shfl_xor_sync(0xffffffff, l_b, 2);
    const float inv_a = 1.0f / l_a;
    const float inv_b = 1.0f / l_b;

    const int tA = qi * 64 + wq * 16 + (lane >> 2);
    const int tB = tA + 8;
#pragma unroll
    for (int j = 0; j < 8; j++) {
        const int d = h * HD + j * 8 + 2 * (lane & 3);
        float2 vA = make_float2(oacc[j][0] * inv_a, oacc[j][1] * inv_a);
        float2 vB = make_float2(oacc[j][2] * inv_b, oacc[j][3] * inv_b);
        *reinterpret_cast<float2*>(y + (size_t)(b * TT + tA) * CC + d) = vA;
        *reinterpret_cast<float2*>(y + (size_t)(b * TT + tB) * CC + d) = vB;
    }
}

// ---------------------------------------------------------------------------
extern "C" void kernel_launch(void* const* d_in, const int* in_sizes, int n_in,
                              void* d_out, int out_size)
{
    const float* x     = (const float*)d_in[0];
    const float* w_qkv = (const float*)d_in[1];
    const float* b_qkv = (const float*)d_in[2];
    const float* w_out = (const float*)d_in[3];
    const float* b_out = (const float*)d_in[4];
    float* out = (float*)d_out;

    float* qkv_buf = nullptr;  cudaGetSymbolAddress((void**)&qkv_buf, g_qkv);
    float* y_buf   = nullptr;  cudaGetSymbolAddress((void**)&y_buf,   g_y);
    __nv_bfloat16 *xs, *ys, *wqs, *wos, *qh, *ql, *kh, *kl, *vh, *vl;
    cudaGetSymbolAddress((void**)&xs,  g_xs);
    cudaGetSymbolAddress((void**)&ys,  g_ys);
    cudaGetSymbolAddress((void**)&wqs, g_wqs);
    cudaGetSymbolAddress((void**)&wos, g_wos);
    cudaGetSymbolAddress((void**)&qh,  g_qh);
    cudaGetSymbolAddress((void**)&ql,  g_ql);
    cudaGetSymbolAddress((void**)&kh,  g_kh);
    cudaGetSymbolAddress((void**)&kl,  g_kl);
    cudaGetSymbolAddress((void**)&vh,  g_vh);
    cudaGetSymbolAddress((void**)&vl,  g_vl);

    cudaFuncSetAttribute(attn_mma, cudaFuncAttributeMaxDynamicSharedMemorySize, ATTN_SMEM);

    // Conversions for QKV GEMM
    {
        int n4 = M_ROWS * CC / 4;
        split3_act<<<(n4 + 255) / 256, 256>>>(x, xs, n4);
        dim3 g1(QKV_N / 32, CC / 32);
        tsplit3<<<g1, 256>>>(w_qkv, QKV_N, wqs);
        dim3 g2(CC / 32, CC / 32);
        tsplit3<<<g2, 256>>>(w_out, CC, wos);
    }

    // 1) qkv = x @ w_qkv + b_qkv  (bf16 HMMA, K'=3072)
    {
        dim3 grid(QKV_N / 128, M_ROWS / 128);
        gemm_mma<<<grid, 256>>>(QKV_N, xs, wqs, b_qkv, qkv_buf);
    }

    // 2) split qkv into head-major hi/lo operands
    {
        int n = M_ROWS * 768;
        split6<<<(n + 255) / 256, 256>>>(qkv_buf, qh, ql, kh, kl, vh, vl);
    }

    // 3) flash attention on tensor cores -> y
    {
        attn_mma<<<BB * HH * NQT, 128, ATTN_SMEM>>>(qh, ql, kh, kl, vh, vl, y_buf);
    }

    // 4) split y, then out = y @ w_out + b_out
    {
        int n4 = M_ROWS * CC / 4;
        split3_act<<<(n4 + 255) / 256, 256>>>(y_buf, ys, n4);
        dim3 grid(CC / 128, M_ROWS / 128);
        gemm_mma<<<grid, 256>>>(CC, ys, wos, b_out, out);
    }
}

// round 7
// speedup vs baseline: 3.6376x; 1.1784x over previous
#include <cuda_runtime.h>
#include <cuda_bf16.h>
#include <math.h>
#include <stdint.h>

// Problem constants
#define BB 2
#define TT 2048
#define CC 1024
#define HH 16
#define HD 64
#define M_ROWS (BB*TT)        // 4096
#define QKV_N  (3*CC)         // 3072
#define K3     (3*CC)         // augmented K = 3072

// ---------------------------------------------------------------------------
// Scratch (__device__ globals; no cudaMalloc allowed)
// ---------------------------------------------------------------------------
__device__ __nv_bfloat16 g_xs [(size_t)M_ROWS * K3];         // x split3   [M, 3K]
__device__ __nv_bfloat16 g_ys [(size_t)M_ROWS * K3];         // attn out split3 [M, 3K]
__device__ __nv_bfloat16 g_wqs[(size_t)QKV_N * K3];          // w_qkv^T split3
__device__ __nv_bfloat16 g_wos[(size_t)CC * K3];             // w_out^T split3
// head-major attention operands [B*H, T, 64]
#define HSZ ((size_t)BB * HH * TT * HD)
__device__ __nv_bfloat16 g_qh[HSZ];
__device__ __nv_bfloat16 g_ql[HSZ];
__device__ __nv_bfloat16 g_kh[HSZ];
__device__ __nv_bfloat16 g_kl[HSZ];
__device__ __nv_bfloat16 g_vh[HSZ];
__device__ __nv_bfloat16 g_vl[HSZ];

// ---------------------------------------------------------------------------
// PTX helpers (sm_80+ baseline: mma.sync bf16, ldmatrix, cp.async)
// ---------------------------------------------------------------------------
__device__ __forceinline__ uint32_t smem_u32(const void* p) {
    uint32_t a;
    asm("{ .reg .u64 t; cvta.to.shared.u64 t, %1; cvt.u32.u64 %0, t; }" : "=r"(a) : "l"(p));
    return a;
}
__device__ __forceinline__ void cp16(uint32_t dst, const void* src) {
    asm volatile("cp.async.cg.shared.global [%0], [%1], 16;" :: "r"(dst), "l"(src));
}
#define CP_COMMIT() asm volatile("cp.async.commit_group;" ::: "memory")
#define CP_WAIT(n)  asm volatile("cp.async.wait_group %0;" :: "n"(n) : "memory")

__device__ __forceinline__ void ldsm4(uint32_t* r, uint32_t addr) {
    asm volatile("ldmatrix.sync.aligned.m8n8.x4.shared.b16 {%0,%1,%2,%3}, [%4];"
        : "=r"(r[0]), "=r"(r[1]), "=r"(r[2]), "=r"(r[3]) : "r"(addr));
}
__device__ __forceinline__ void ldsm4t(uint32_t* r, uint32_t addr) {
    asm volatile("ldmatrix.sync.aligned.m8n8.x4.trans.shared.b16 {%0,%1,%2,%3}, [%4];"
        : "=r"(r[0]), "=r"(r[1]), "=r"(r[2]), "=r"(r[3]) : "r"(addr));
}
__device__ __forceinline__ void mma16816(float* d, const uint32_t* a, const uint32_t* b) {
    asm volatile(
        "mma.sync.aligned.m16n8k16.row.col.f32.bf16.bf16.f32 "
        "{%0,%1,%2,%3}, {%4,%5,%6,%7}, {%8,%9}, {%0,%1,%2,%3};"
        : "+f"(d[0]), "+f"(d[1]), "+f"(d[2]), "+f"(d[3])
        : "r"(a[0]), "r"(a[1]), "r"(a[2]), "r"(a[3]), "r"(b[0]), "r"(b[1]));
}
__device__ __forceinline__ uint32_t pack_bf16x2(__nv_bfloat16 a, __nv_bfloat16 b) {
    __nv_bfloat162 h = __halves2bfloat162(a, b);
    return *reinterpret_cast<uint32_t*>(&h);
}
__device__ __forceinline__ void split1(float v, __nv_bfloat16& h, __nv_bfloat16& l) {
    h = __float2bfloat16(v);
    l = __float2bfloat16(v - __bfloat162float(h));
}

// ---------------------------------------------------------------------------
// Conversion kernels for the GEMM inputs
// ---------------------------------------------------------------------------
__global__ void split3_act(const float* __restrict__ in,
                           __nv_bfloat16* __restrict__ out, int n4)
{
    int i = blockIdx.x * blockDim.x + threadIdx.x;
    if (i >= n4) return;
    int m  = i >> 8;
    int kc = i & 255;
    float4 v = reinterpret_cast<const float4*>(in)[i];
    __nv_bfloat16 h[4], l[4];
    float f[4] = {v.x, v.y, v.z, v.w};
#pragma unroll
    for (int j = 0; j < 4; j++) split1(f[j], h[j], l[j]);
    __nv_bfloat162 hp0(h[0], h[1]), hp1(h[2], h[3]);
    __nv_bfloat162 lp0(l[0], l[1]), lp1(l[2], l[3]);
    __nv_bfloat162* o = reinterpret_cast<__nv_bfloat162*>(out + (size_t)m * K3 + kc * 4);
    o[0] = hp0; o[1] = hp1;
    o[CC / 2 + 0] = hp0; o[CC / 2 + 1] = hp1;
    o[CC + 0] = lp0; o[CC + 1] = lp1;
}

__global__ __launch_bounds__(256) void tsplit3(
    const float* __restrict__ W, int N, __nv_bfloat16* __restrict__ out)
{
    __shared__ float t[32][33];
    const int nb = blockIdx.x * 32;
    const int kb = blockIdx.y * 32;
    const int tx = threadIdx.x & 31;
    const int ty = threadIdx.x >> 5;
    for (int r = ty; r < 32; r += 8)
        t[r][tx] = W[(size_t)(kb + r) * N + nb + tx];
    __syncthreads();
    for (int r = ty; r < 32; r += 8) {
        float v = t[tx][r];
        __nv_bfloat16 h, l;
        split1(v, h, l);
        size_t o = (size_t)(nb + r) * K3 + kb + tx;
        out[o]          = h;
        out[o + CC]     = l;
        out[o + 2 * CC] = h;
    }
}

// ---------------------------------------------------------------------------
// bf16 HMMA GEMM: C[M,N] = A'[M,3K] @ B'[N,3K]^T + bias[N]
// 128x128 tile, BK=64, 8 warps (2x4), warp tile 64x32, double-buffered.
// MODE 0: write fp32 C. MODE 1 (QKV): write head-major split q/k/v directly.
// ---------------------------------------------------------------------------
#define GP 144
#define GATILE (128 * GP)        // 18432
#define GSTAGE (2 * GATILE)      // 36864 (A + B)
#define GEMM_SMEM (2 * GSTAGE)   // 73728
#define NKB (K3 / 64)            // 48

template <int MODE>
__global__ __launch_bounds__(256) void gemm_mma(
    int N,
    const __nv_bfloat16* __restrict__ A,
    const __nv_bfloat16* __restrict__ B,
    const float* __restrict__ bias,
    float* __restrict__ C,
    __nv_bfloat16* __restrict__ qh, __nv_bfloat16* __restrict__ ql,
    __nv_bfloat16* __restrict__ kh, __nv_bfloat16* __restrict__ kl,
    __nv_bfloat16* __restrict__ vh, __nv_bfloat16* __restrict__ vl)
{
    extern __shared__ char smem[];
    const uint32_t sbase = smem_u32(smem);

    const int tid  = threadIdx.x;
    const int lane = tid & 31;
    const int wid  = tid >> 5;
    const int wm   = wid >> 2;
    const int wn   = wid & 3;
    const int m0   = blockIdx.y * 128;
    const int n0   = blockIdx.x * 128;

    float acc[4][4][4];
#pragma unroll
    for (int mi = 0; mi < 4; mi++)
#pragma unroll
        for (int nj = 0; nj < 4; nj++)
#pragma unroll
            for (int r = 0; r < 4; r++) acc[mi][nj][r] = 0.0f;

    auto load_stage = [&](int kb, int st) {
        const uint32_t sa = sbase + st * GSTAGE;
        const uint32_t sbm = sa + GATILE;
        const int k0 = kb * 64;
#pragma unroll
        for (int j = 0; j < 4; j++) {
            int id = tid + 256 * j;          // 0..1023
            int r = id >> 3;                 // 0..127
            int c = id & 7;                  // 0..7
            cp16(sa + r * GP + c * 16, A + (size_t)(m0 + r) * K3 + k0 + c * 8);
        }
#pragma unroll
        for (int j = 0; j < 4; j++) {
            int id = tid + 256 * j;
            int r = id >> 3;
            int c = id & 7;
            cp16(sbm + r * GP + c * 16, B + (size_t)(n0 + r) * K3 + k0 + c * 8);
        }
        CP_COMMIT();
    };

    load_stage(0, 0);

    for (int kb = 0; kb < NKB; kb++) {
        const int st = kb & 1;
        if (kb + 1 < NKB) load_stage(kb + 1, st ^ 1);
        if (kb + 1 < NKB) { CP_WAIT(1); } else { CP_WAIT(0); }
        __syncthreads();

        const uint32_t sa = sbase + st * GSTAGE;
        const uint32_t sbm = sa + GATILE;

#pragma unroll
        for (int ks = 0; ks < 4; ks++) {
            uint32_t af[4][4];
#pragma unroll
            for (int mi = 0; mi < 4; mi++) {
                uint32_t addr = sa + (wm * 64 + mi * 16 + (lane & 15)) * GP
                              + ks * 32 + ((lane >> 4) * 16);
                ldsm4(af[mi], addr);
            }
            uint32_t bf[2][4];
#pragma unroll
            for (int nj2 = 0; nj2 < 2; nj2++) {
                int nrow = wn * 32 + nj2 * 16 + (lane & 7) + (((lane >> 4) & 1) * 8);
                uint32_t addr = sbm + nrow * GP + ks * 32 + (((lane >> 3) & 1) * 16);
                ldsm4(bf[nj2], addr);
            }
#pragma unroll
            for (int mi = 0; mi < 4; mi++)
#pragma unroll
                for (int nj = 0; nj < 4; nj++)
                    mma16816(acc[mi][nj], af[mi], &bf[nj >> 1][(nj & 1) * 2]);
        }
        __syncthreads();
    }

    // Epilogue
#pragma unroll
    for (int mi = 0; mi < 4; mi++) {
#pragma unroll
        for (int nj = 0; nj < 4; nj++) {
            const int row = m0 + wm * 64 + mi * 16 + (lane >> 2);
            const int col = n0 + wn * 32 + nj * 8 + 2 * (lane & 3);
            float2 bz = *reinterpret_cast<const float2*>(bias + col);
            float2 v0 = make_float2(acc[mi][nj][0] + bz.x, acc[mi][nj][1] + bz.y);
            float2 v1 = make_float2(acc[mi][nj][2] + bz.x, acc[mi][nj][3] + bz.y);
            if (MODE == 0) {
                *reinterpret_cast<float2*>(C + (size_t)row * N + col) = v0;
                *reinterpret_cast<float2*>(C + (size_t)(row + 8) * N + col) = v1;
            } else {
                const int seg = col >> 10;       // 0=q 1=k 2=v
                const int hc  = col & 1023;
                const int h   = hc >> 6;
                const int d   = hc & 63;
                if (seg == 0) { v0.x *= 0.125f; v0.y *= 0.125f; v1.x *= 0.125f; v1.y *= 0.125f; }
                __nv_bfloat16* hp = (seg == 0) ? qh : (seg == 1) ? kh : vh;
                __nv_bfloat16* lp = (seg == 0) ? ql : (seg == 1) ? kl : vl;
#pragma unroll
                for (int rr = 0; rr < 2; rr++) {
                    const int m = row + rr * 8;
                    const int b = m >> 11, t = m & 2047;
                    const size_t dst = (((size_t)(b * HH + h)) * TT + t) * HD + d;
                    float2 v = rr ? v1 : v0;
                    __nv_bfloat16 h0, l0, h1, l1;
                    split1(v.x, h0, l0);
                    split1(v.y, h1, l1);
                    *reinterpret_cast<uint32_t*>(hp + dst) = pack_bf16x2(h0, h1);
                    *reinterpret_cast<uint32_t*>(lp + dst) = pack_bf16x2(l0, l1);
                }
            }
        }
    }
}

// ---------------------------------------------------------------------------
// Flash attention on HMMA, split-bf16 (3-term) for QK and PV.
// 128 threads (4 warps), Q tile 64, KV tiles 64, double-buffered.
// Epilogue writes split3 rows of y directly: [yh | yh | yl].
// ---------------------------------------------------------------------------
#define AP 144
#define ATILE_B (64 * AP)            // 9216
#define Q_H 0
#define Q_L ATILE_B
#define STG (2 * ATILE_B)            // 18432
#define KV_STAGE (4 * ATILE_B)       // 36864
#define ATTN_SMEM (STG + 2 * KV_STAGE)  // 92160
#define NQT (TT / 64)                // 32

__global__ __launch_bounds__(128) void attn_mma(
    const __nv_bfloat16* __restrict__ Qh, const __nv_bfloat16* __restrict__ Ql,
    const __nv_bfloat16* __restrict__ Kh, const __nv_bfloat16* __restrict__ Kl,
    const __nv_bfloat16* __restrict__ Vh, const __nv_bfloat16* __restrict__ Vl,
    __nv_bfloat16* __restrict__ ys)
{
    extern __shared__ char sm[];
    const uint32_t sb = smem_u32(sm);
    const int tid  = threadIdx.x;
    const int lane = tid & 31;
    const int wq   = tid >> 5;
    const int bx   = blockIdx.x;
    const int qi   = (NQT - 1) - (bx >> 5);    // heavy tiles first
    const int bh   = bx & 31;
    const int b    = bh >> 4;
    const int h    = bh & 15;
    const size_t hoff = (size_t)bh * TT * HD;

#pragma unroll
    for (int j = 0; j < 4; j++) {
        int id = tid + 128 * j;
        int r = id >> 3, c = id & 7;
        const size_t g = hoff + (size_t)(qi * 64 + r) * HD + c * 8;
        cp16(sb + Q_H + r * AP + c * 16, Qh + g);
        cp16(sb + Q_L + r * AP + c * 16, Ql + g);
    }
    CP_COMMIT();

    auto load_kv = [&](int kt, int st) {
        const uint32_t s0 = sb + STG + st * KV_STAGE;
        const int t0 = kt * 64;
#pragma unroll
        for (int j = 0; j < 4; j++) {
            int id = tid + 128 * j;
            int r = id >> 3, c = id & 7;
            const size_t g = hoff + (size_t)(t0 + r) * HD + c * 8;
            const uint32_t so = r * AP + c * 16;
            cp16(s0 + 0 * ATILE_B + so, Kh + g);
            cp16(s0 + 1 * ATILE_B + so, Kl + g);
            cp16(s0 + 2 * ATILE_B + so, Vh + g);
            cp16(s0 + 3 * ATILE_B + so, Vl + g);
        }
        CP_COMMIT();
    };

    load_kv(0, 0);
    CP_WAIT(0);
    __syncthreads();

    uint32_t qhf[4][4], qlf[4][4];
#pragma unroll
    for (int ks = 0; ks < 4; ks++) {
        uint32_t ao = (wq * 16 + (lane & 15)) * AP + (ks * 16 + (lane >> 4) * 8) * 2;
        ldsm4(qhf[ks], sb + Q_H + ao);
        ldsm4(qlf[ks], sb + Q_L + ao);
    }

    float oacc[8][4];
#pragma unroll
    for (int j = 0; j < 8; j++)
#pragma unroll
        for (int r = 0; r < 4; r++) oacc[j][r] = 0.0f;
    float m_a = -1e30f, m_b = -1e30f, l_a = 0.0f, l_b = 0.0f;

    for (int kt = 0; kt <= qi; kt++) {
        const int st = kt & 1;
        if (kt < qi) load_kv(kt + 1, st ^ 1);

        const uint32_t s0 = sb + STG + st * KV_STAGE;

        float sacc[8][4];
#pragma unroll
        for (int j = 0; j < 8; j++)
#pragma unroll
            for (int r = 0; r < 4; r++) sacc[j][r] = 0.0f;

#pragma unroll
        for (int ks = 0; ks < 4; ks++) {
#pragma unroll
            for (int jp = 0; jp < 4; jp++) {
                uint32_t ro = ((2 * jp + ((lane >> 4) & 1)) * 8 + (lane & 7)) * AP
                            + (ks * 16 + ((lane >> 3) & 1) * 8) * 2;
                uint32_t kbh[4], kbl[4];
                ldsm4(kbh, s0 + 0 * ATILE_B + ro);
                ldsm4(kbl, s0 + 1 * ATILE_B + ro);
                mma16816(sacc[2 * jp],     qhf[ks], &kbh[0]);
                mma16816(sacc[2 * jp],     qlf[ks], &kbh[0]);
                mma16816(sacc[2 * jp],     qhf[ks], &kbl[0]);
                mma16816(sacc[2 * jp + 1], qhf[ks], &kbh[2]);
                mma16816(sacc[2 * jp + 1], qlf[ks], &kbh[2]);
                mma16816(sacc[2 * jp + 1], qhf[ks], &kbl[2]);
            }
        }

        if (kt == qi) {
            const int rA = wq * 16 + (lane >> 2);
            const int rB = rA + 8;
#pragma unroll
            for (int j = 0; j < 8; j++) {
                const int cl = j * 8 + 2 * (lane & 3);
                if (cl     > rA) sacc[j][0] = -1e30f;
                if (cl + 1 > rA) sacc[j][1] = -1e30f;
                if (cl     > rB) sacc[j][2] = -1e30f;
                if (cl + 1 > rB) sacc[j][3] = -1e30f;
            }
        }

        float mx_a = -1e30f, mx_b = -1e30f;
#pragma unroll
        for (int j = 0; j < 8; j++) {
            mx_a = fmaxf(mx_a, fmaxf(sacc[j][0], sacc[j][1]));
            mx_b = fmaxf(mx_b, fmaxf(sacc[j][2], sacc[j][3]));
        }
        mx_a = fmaxf(mx_a, __shfl_xor_sync(0xffffffff, mx_a, 1));
        mx_a = fmaxf(mx_a, __shfl_xor_sync(0xffffffff, mx_a, 2));
        mx_b = fmaxf(mx_b, __shfl_xor_sync(0xffffffff, mx_b, 1));
        mx_b = fmaxf(mx_b, __shfl_xor_sync(0xffffffff, mx_b, 2));

        const float mn_a = fmaxf(m_a, mx_a);
        const float mn_b = fmaxf(m_b, mx_b);
        const float al_a = __expf(m_a - mn_a);
        const float al_b = __expf(m_b - mn_b);
        l_a *= al_a; l_b *= al_b;
        m_a = mn_a;  m_b = mn_b;
#pragma unroll
        for (int j = 0; j < 8; j++) {
            oacc[j][0] *= al_a; oacc[j][1] *= al_a;
            oacc[j][2] *= al_b; oacc[j][3] *= al_b;
        }

        uint32_t pha[8], phb[8], pla[8], plb[8];
#pragma unroll
        for (int j = 0; j < 8; j++) {
            float p0 = __expf(sacc[j][0] - mn_a);
            float p1 = __expf(sacc[j][1] - mn_a);
            float p2 = __expf(sacc[j][2] - mn_b);
            float p3 = __expf(sacc[j][3] - mn_b);
            l_a += p0 + p1;
            l_b += p2 + p3;
            __nv_bfloat16 h0, l0, h1, l1, h2, l2, h3, l3;
            split1(p0, h0, l0); split1(p1, h1, l1);
            split1(p2, h2, l2); split1(p3, h3, l3);
            pha[j] = pack_bf16x2(h0, h1);
            phb[j] = pack_bf16x2(h2, h3);
            pla[j] = pack_bf16x2(l0, l1);
            plb[j] = pack_bf16x2(l2, l3);
        }

#pragma unroll
        for (int ks = 0; ks < 4; ks++) {
            uint32_t Ah[4] = {pha[2 * ks], phb[2 * ks], pha[2 * ks + 1], phb[2 * ks + 1]};
            uint32_t Al[4] = {pla[2 * ks], plb[2 * ks], pla[2 * ks + 1], plb[2 * ks + 1]};
#pragma unroll
            for (int dp = 0; dp < 4; dp++) {
                uint32_t vo = (ks * 16 + (lane & 15)) * AP
                            + (dp * 16 + ((lane >> 4) & 1) * 8) * 2;
                uint32_t vbh[4], vbl[4];
                ldsm4t(vbh, s0 + 2 * ATILE_B + vo);
                ldsm4t(vbl, s0 + 3 * ATILE_B + vo);
                mma16816(oacc[2 * dp],     Ah, &vbh[0]);
                mma16816(oacc[2 * dp],     Al, &vbh[0]);
                mma16816(oacc[2 * dp],     Ah, &vbl[0]);
                mma16816(oacc[2 * dp + 1], Ah, &vbh[2]);
                mma16816(oacc[2 * dp + 1], Al, &vbh[2]);
                mma16816(oacc[2 * dp + 1], Ah, &vbl[2]);
            }
        }

        if (kt < qi) { CP_WAIT(0); }
        __syncthreads();
    }

    l_a += __shfl_xor_sync(0xffffffff, l_a, 1);
    l_a += __shfl_xor_sync(0xffffffff, l_a, 2);
    l_b += __shfl_xor_sync(0xffffffff, l_b, 1);
    l_b += __shfl_xor_sync(0xffffffff, l_b, 2);
    const float inv_a = 1.0f / l_a;
    const float inv_b = 1.0f / l_b;

    const int tA = qi * 64 + wq * 16 + (lane >> 2);
    const int tB = tA + 8;
    const size_t rowA = (size_t)(b * TT + tA) * K3;
    const size_t rowB = (size_t)(b * TT + tB) * K3;
#pragma unroll
    for (int j = 0; j < 8; j++) {
        const int d = h * HD + j * 8 + 2 * (lane & 3);
        float2 vA = make_float2(oacc[j][0] * inv_a, oacc[j][1] * inv_a);
        float2 vB = make_float2(oacc[j][2] * inv_b, oacc[j][3] * inv_b);
        __nv_bfloat16 hA0, lA0, hA1, lA1, hB0, lB0, hB1, lB1;
        split1(vA.x, hA0, lA0); split1(vA.y, hA1, lA1);
        split1(vB.x, hB0, lB0); split1(vB.y, hB1, lB1);
        uint32_t hpA = pack_bf16x2(hA0, hA1), lpA = pack_bf16x2(lA0, lA1);
        uint32_t hpB = pack_bf16x2(hB0, hB1), lpB = pack_bf16x2(lB0, lB1);
        *reinterpret_cast<uint32_t*>(ys + rowA + d)          = hpA;
        *reinterpret_cast<uint32_t*>(ys + rowA + CC + d)     = hpA;
        *reinterpret_cast<uint32_t*>(ys + rowA + 2 * CC + d) = lpA;
        *reinterpret_cast<uint32_t*>(ys + rowB + d)          = hpB;
        *reinterpret_cast<uint32_t*>(ys + rowB + CC + d)     = hpB;
        *reinterpret_cast<uint32_t*>(ys + rowB + 2 * CC + d) = lpB;
    }
}

// ---------------------------------------------------------------------------
extern "C" void kernel_launch(void* const* d_in, const int* in_sizes, int n_in,
                              void* d_out, int out_size)
{
    const float* x     = (const float*)d_in[0];
    const float* w_qkv = (const float*)d_in[1];
    const float* b_qkv = (const float*)d_in[2];
    const float* w_out = (const float*)d_in[3];
    const float* b_out = (const float*)d_in[4];
    float* out = (float*)d_out;

    __nv_bfloat16 *xs, *ys, *wqs, *wos, *qh, *ql, *kh, *kl, *vh, *vl;
    cudaGetSymbolAddress((void**)&xs,  g_xs);
    cudaGetSymbolAddress((void**)&ys,  g_ys);
    cudaGetSymbolAddress((void**)&wqs, g_wqs);
    cudaGetSymbolAddress((void**)&wos, g_wos);
    cudaGetSymbolAddress((void**)&qh,  g_qh);
    cudaGetSymbolAddress((void**)&ql,  g_ql);
    cudaGetSymbolAddress((void**)&kh,  g_kh);
    cudaGetSymbolAddress((void**)&kl,  g_kl);
    cudaGetSymbolAddress((void**)&vh,  g_vh);
    cudaGetSymbolAddress((void**)&vl,  g_vl);

    cudaFuncSetAttribute(gemm_mma<0>, cudaFuncAttributeMaxDynamicSharedMemorySize, GEMM_SMEM);
    cudaFuncSetAttribute(gemm_mma<1>, cudaFuncAttributeMaxDynamicSharedMemorySize, GEMM_SMEM);
    cudaFuncSetAttribute(attn_mma, cudaFuncAttributeMaxDynamicSharedMemorySize, ATTN_SMEM);

    // Input conversions
    {
        int n4 = M_ROWS * CC / 4;
        split3_act<<<(n4 + 255) / 256, 256>>>(x, xs, n4);
        dim3 g1(QKV_N / 32, CC / 32);
        tsplit3<<<g1, 256>>>(w_qkv, QKV_N, wqs);
        dim3 g2(CC / 32, CC / 32);
        tsplit3<<<g2, 256>>>(w_out, CC, wos);
    }

    // 1) QKV GEMM, epilogue writes head-major split q/k/v directly
    {
        dim3 grid(QKV_N / 128, M_ROWS / 128);
        gemm_mma<1><<<grid, 256, GEMM_SMEM>>>(QKV_N, xs, wqs, b_qkv, nullptr,
                                              qh, ql, kh, kl, vh, vl);
    }

    // 2) flash attention -> ys (split3 layout)
    {
        attn_mma<<<BB * HH * NQT, 128, ATTN_SMEM>>>(qh, ql, kh, kl, vh, vl, ys);
    }

    // 3) out = y @ w_out + b_out
    {
        dim3 grid(CC / 128, M_ROWS / 128);
        gemm_mma<0><<<grid, 256, GEMM_SMEM>>>(CC, ys, wos, b_out, out,
                                              nullptr, nullptr, nullptr, nullptr, nullptr, nullptr);
    }
}

// round 8
// speedup vs baseline: 4.0021x; 1.1002x over previous
#include <cuda_runtime.h>
#include <cuda_bf16.h>
#include <math.h>
#include <stdint.h>

// Problem constants
#define BB 2
#define TT 2048
#define CC 1024
#define HH 16
#define HD 64
#define M_ROWS (BB*TT)        // 4096
#define QKV_N  (3*CC)         // 3072
#define K3     (3*CC)         // augmented K = 3072

// ---------------------------------------------------------------------------
// Scratch (__device__ globals; no cudaMalloc allowed)
// ---------------------------------------------------------------------------
__device__ __nv_bfloat16 g_xs [(size_t)M_ROWS * K3];
__device__ __nv_bfloat16 g_ys [(size_t)M_ROWS * K3];
__device__ __nv_bfloat16 g_wqs[(size_t)QKV_N * K3];
__device__ __nv_bfloat16 g_wos[(size_t)CC * K3];
#define HSZ ((size_t)BB * HH * TT * HD)
__device__ __nv_bfloat16 g_qh[HSZ];
__device__ __nv_bfloat16 g_ql[HSZ];
__device__ __nv_bfloat16 g_kh[HSZ];
__device__ __nv_bfloat16 g_kl[HSZ];
__device__ __nv_bfloat16 g_vh[HSZ];
__device__ __nv_bfloat16 g_vl[HSZ];

// ---------------------------------------------------------------------------
// PTX helpers
// ---------------------------------------------------------------------------
__device__ __forceinline__ uint32_t smem_u32(const void* p) {
    uint32_t a;
    asm("{ .reg .u64 t; cvta.to.shared.u64 t, %1; cvt.u32.u64 %0, t; }" : "=r"(a) : "l"(p));
    return a;
}
__device__ __forceinline__ void cp16(uint32_t dst, const void* src) {
    asm volatile("cp.async.cg.shared.global [%0], [%1], 16;" :: "r"(dst), "l"(src));
}
#define CP_COMMIT() asm volatile("cp.async.commit_group;" ::: "memory")
#define CP_WAIT(n)  asm volatile("cp.async.wait_group %0;" :: "n"(n) : "memory")

__device__ __forceinline__ void ldsm4(uint32_t* r, uint32_t addr) {
    asm volatile("ldmatrix.sync.aligned.m8n8.x4.shared.b16 {%0,%1,%2,%3}, [%4];"
        : "=r"(r[0]), "=r"(r[1]), "=r"(r[2]), "=r"(r[3]) : "r"(addr));
}
__device__ __forceinline__ void ldsm4t(uint32_t* r, uint32_t addr) {
    asm volatile("ldmatrix.sync.aligned.m8n8.x4.trans.shared.b16 {%0,%1,%2,%3}, [%4];"
        : "=r"(r[0]), "=r"(r[1]), "=r"(r[2]), "=r"(r[3]) : "r"(addr));
}
__device__ __forceinline__ void mma16816(float* d, const uint32_t* a, const uint32_t* b) {
    asm volatile(
        "mma.sync.aligned.m16n8k16.row.col.f32.bf16.bf16.f32 "
        "{%0,%1,%2,%3}, {%4,%5,%6,%7}, {%8,%9}, {%0,%1,%2,%3};"
        : "+f"(d[0]), "+f"(d[1]), "+f"(d[2]), "+f"(d[3])
        : "r"(a[0]), "r"(a[1]), "r"(a[2]), "r"(a[3]), "r"(b[0]), "r"(b[1]));
}
__device__ __forceinline__ uint32_t pack_bf16x2(__nv_bfloat16 a, __nv_bfloat16 b) {
    __nv_bfloat162 h = __halves2bfloat162(a, b);
    return *reinterpret_cast<uint32_t*>(&h);
}
__device__ __forceinline__ void split1(float v, __nv_bfloat16& h, __nv_bfloat16& l) {
    h = __float2bfloat16(v);
    l = __float2bfloat16(v - __bfloat162float(h));
}

// ---------------------------------------------------------------------------
// Conversion kernels for the GEMM inputs
// ---------------------------------------------------------------------------
__global__ void split3_act(const float* __restrict__ in,
                           __nv_bfloat16* __restrict__ out, int n4)
{
    int i = blockIdx.x * blockDim.x + threadIdx.x;
    if (i >= n4) return;
    int m  = i >> 8;
    int kc = i & 255;
    float4 v = reinterpret_cast<const float4*>(in)[i];
    __nv_bfloat16 h[4], l[4];
    float f[4] = {v.x, v.y, v.z, v.w};
#pragma unroll
    for (int j = 0; j < 4; j++) split1(f[j], h[j], l[j]);
    __nv_bfloat162 hp0(h[0], h[1]), hp1(h[2], h[3]);
    __nv_bfloat162 lp0(l[0], l[1]), lp1(l[2], l[3]);
    __nv_bfloat162* o = reinterpret_cast<__nv_bfloat162*>(out + (size_t)m * K3 + kc * 4);
    o[0] = hp0; o[1] = hp1;
    o[CC / 2 + 0] = hp0; o[CC / 2 + 1] = hp1;
    o[CC + 0] = lp0; o[CC + 1] = lp1;
}

__global__ __launch_bounds__(256) void tsplit3(
    const float* __restrict__ W, int N, __nv_bfloat16* __restrict__ out)
{
    __shared__ float t[32][33];
    const int nb = blockIdx.x * 32;
    const int kb = blockIdx.y * 32;
    const int tx = threadIdx.x & 31;
    const int ty = threadIdx.x >> 5;
    for (int r = ty; r < 32; r += 8)
        t[r][tx] = W[(size_t)(kb + r) * N + nb + tx];
    __syncthreads();
    for (int r = ty; r < 32; r += 8) {
        float v = t[tx][r];
        __nv_bfloat16 h, l;
        split1(v, h, l);
        size_t o = (size_t)(nb + r) * K3 + kb + tx;
        out[o]          = h;
        out[o + CC]     = l;
        out[o + 2 * CC] = h;
    }
}

// ---------------------------------------------------------------------------
// bf16 HMMA GEMM: C[M,N] = A'[M,3K] @ B'[N,3K]^T + bias[N]
// 128x128 tile, BK=64, 8 warps (2x4), 3-stage cp.async, swizzled smem (128B
// rows, 16B unit index XOR row&7 -> bank-conflict-free cp.async + ldmatrix).
// ---------------------------------------------------------------------------
#define GATILE 16384             // 128 rows * 128 B
#define GSTAGE (2 * GATILE)      // 32768 (A + B)
#define GEMM_SMEM (3 * GSTAGE)   // 98304
#define NKB (K3 / 64)            // 48

template <int MODE>
__global__ __launch_bounds__(256) void gemm_mma(
    int N,
    const __nv_bfloat16* __restrict__ A,
    const __nv_bfloat16* __restrict__ B,
    const float* __restrict__ bias,
    float* __restrict__ C,
    __nv_bfloat16* __restrict__ qh, __nv_bfloat16* __restrict__ ql,
    __nv_bfloat16* __restrict__ kh, __nv_bfloat16* __restrict__ kl,
    __nv_bfloat16* __restrict__ vh, __nv_bfloat16* __restrict__ vl)
{
    extern __shared__ char smem[];
    const uint32_t sbase = smem_u32(smem);

    const int tid  = threadIdx.x;
    const int lane = tid & 31;
    const int wid  = tid >> 5;
    const int wm   = wid >> 2;
    const int wn   = wid & 3;
    const int m0   = blockIdx.y * 128;
    const int n0   = blockIdx.x * 128;

    float acc[4][4][4];
#pragma unroll
    for (int mi = 0; mi < 4; mi++)
#pragma unroll
        for (int nj = 0; nj < 4; nj++)
#pragma unroll
            for (int r = 0; r < 4; r++) acc[mi][nj][r] = 0.0f;

    auto load_stage = [&](int kb, int st) {
        const uint32_t sa  = sbase + st * GSTAGE;
        const uint32_t sbm = sa + GATILE;
        const int k0 = kb * 64;
#pragma unroll
        for (int j = 0; j < 4; j++) {
            int id = tid + 256 * j;          // 0..1023
            int r = id >> 3;                 // 0..127
            int c = id & 7;                  // 16B unit 0..7
            int cs = c ^ (r & 7);
            cp16(sa + r * 128 + cs * 16, A + (size_t)(m0 + r) * K3 + k0 + c * 8);
        }
#pragma unroll
        for (int j = 0; j < 4; j++) {
            int id = tid + 256 * j;
            int r = id >> 3;
            int c = id & 7;
            int cs = c ^ (r & 7);
            cp16(sbm + r * 128 + cs * 16, B + (size_t)(n0 + r) * K3 + k0 + c * 8);
        }
        CP_COMMIT();
    };

    load_stage(0, 0);
    load_stage(1, 1);

    for (int kb = 0; kb < NKB; kb++) {
        const int st = kb % 3;
        if (kb + 2 < NKB) {
            load_stage(kb + 2, (kb + 2) % 3);
            CP_WAIT(2);
        } else if (kb + 1 < NKB) {
            CP_WAIT(1);
        } else {
            CP_WAIT(0);
        }
        __syncthreads();

        const uint32_t sa  = sbase + st * GSTAGE;
        const uint32_t sbm = sa + GATILE;

#pragma unroll
        for (int ks = 0; ks < 4; ks++) {
            uint32_t af[4][4];
#pragma unroll
            for (int mi = 0; mi < 4; mi++) {
                const int r = wm * 64 + mi * 16 + (lane & 15);
                const int u = (ks * 2 + (lane >> 4)) ^ (r & 7);
                ldsm4(af[mi], sa + r * 128 + u * 16);
            }
            uint32_t bf[2][4];
#pragma unroll
            for (int nj2 = 0; nj2 < 2; nj2++) {
                const int r = wn * 32 + nj2 * 16 + (lane & 7) + (((lane >> 4) & 1) * 8);
                const int u = (ks * 2 + ((lane >> 3) & 1)) ^ (r & 7);
                ldsm4(bf[nj2], sbm + r * 128 + u * 16);
            }
#pragma unroll
            for (int mi = 0; mi < 4; mi++)
#pragma unroll
                for (int nj = 0; nj < 4; nj++)
                    mma16816(acc[mi][nj], af[mi], &bf[nj >> 1][(nj & 1) * 2]);
        }
        __syncthreads();
    }

    // Epilogue
#pragma unroll
    for (int mi = 0; mi < 4; mi++) {
#pragma unroll
        for (int nj = 0; nj < 4; nj++) {
            const int row = m0 + wm * 64 + mi * 16 + (lane >> 2);
            const int col = n0 + wn * 32 + nj * 8 + 2 * (lane & 3);
            float2 bz = *reinterpret_cast<const float2*>(bias + col);
            float2 v0 = make_float2(acc[mi][nj][0] + bz.x, acc[mi][nj][1] + bz.y);
            float2 v1 = make_float2(acc[mi][nj][2] + bz.x, acc[mi][nj][3] + bz.y);
            if (MODE == 0) {
                *reinterpret_cast<float2*>(C + (size_t)row * N + col) = v0;
                *reinterpret_cast<float2*>(C + (size_t)(row + 8) * N + col) = v1;
            } else {
                const int seg = col >> 10;
                const int hc  = col & 1023;
                const int h   = hc >> 6;
                const int d   = hc & 63;
                if (seg == 0) { v0.x *= 0.125f; v0.y *= 0.125f; v1.x *= 0.125f; v1.y *= 0.125f; }
                __nv_bfloat16* hp = (seg == 0) ? qh : (seg == 1) ? kh : vh;
                __nv_bfloat16* lp = (seg == 0) ? ql : (seg == 1) ? kl : vl;
#pragma unroll
                for (int rr = 0; rr < 2; rr++) {
                    const int m = row + rr * 8;
                    const int b = m >> 11, t = m & 2047;
                    const size_t dst = (((size_t)(b * HH + h)) * TT + t) * HD + d;
                    float2 v = rr ? v1 : v0;
                    __nv_bfloat16 h0, l0, h1, l1;
                    split1(v.x, h0, l0);
                    split1(v.y, h1, l1);
                    *reinterpret_cast<uint32_t*>(hp + dst) = pack_bf16x2(h0, h1);
                    *reinterpret_cast<uint32_t*>(lp + dst) = pack_bf16x2(l0, l1);
                }
            }
        }
    }
}

// ---------------------------------------------------------------------------
// Flash attention on HMMA, split-bf16 (3-term) for QK and PV (unchanged R7).
// ---------------------------------------------------------------------------
#define AP 144
#define ATILE_B (64 * AP)
#define Q_H 0
#define Q_L ATILE_B
#define STG (2 * ATILE_B)
#define KV_STAGE (4 * ATILE_B)
#define ATTN_SMEM (STG + 2 * KV_STAGE)
#define NQT (TT / 64)

__global__ __launch_bounds__(128) void attn_mma(
    const __nv_bfloat16* __restrict__ Qh, const __nv_bfloat16* __restrict__ Ql,
    const __nv_bfloat16* __restrict__ Kh, const __nv_bfloat16* __restrict__ Kl,
    const __nv_bfloat16* __restrict__ Vh, const __nv_bfloat16* __restrict__ Vl,
    __nv_bfloat16* __restrict__ ys)
{
    extern __shared__ char sm[];
    const uint32_t sb = smem_u32(sm);
    const int tid  = threadIdx.x;
    const int lane = tid & 31;
    const int wq   = tid >> 5;
    const int bx   = blockIdx.x;
    const int qi   = (NQT - 1) - (bx >> 5);
    const int bh   = bx & 31;
    const int b    = bh >> 4;
    const int h    = bh & 15;
    const size_t hoff = (size_t)bh * TT * HD;

#pragma unroll
    for (int j = 0; j < 4; j++) {
        int id = tid + 128 * j;
        int r = id >> 3, c = id & 7;
        const size_t g = hoff + (size_t)(qi * 64 + r) * HD + c * 8;
        cp16(sb + Q_H + r * AP + c * 16, Qh + g);
        cp16(sb + Q_L + r * AP + c * 16, Ql + g);
    }
    CP_COMMIT();

    auto load_kv = [&](int kt, int st) {
        const uint32_t s0 = sb + STG + st * KV_STAGE;
        const int t0 = kt * 64;
#pragma unroll
        for (int j = 0; j < 4; j++) {
            int id = tid + 128 * j;
            int r = id >> 3, c = id & 7;
            const size_t g = hoff + (size_t)(t0 + r) * HD + c * 8;
            const uint32_t so = r * AP + c * 16;
            cp16(s0 + 0 * ATILE_B + so, Kh + g);
            cp16(s0 + 1 * ATILE_B + so, Kl + g);
            cp16(s0 + 2 * ATILE_B + so, Vh + g);
            cp16(s0 + 3 * ATILE_B + so, Vl + g);
        }
        CP_COMMIT();
    };

    load_kv(0, 0);
    CP_WAIT(0);
    __syncthreads();

    uint32_t qhf[4][4], qlf[4][4];
#pragma unroll
    for (int ks = 0; ks < 4; ks++) {
        uint32_t ao = (wq * 16 + (lane & 15)) * AP + (ks * 16 + (lane >> 4) * 8) * 2;
        ldsm4(qhf[ks], sb + Q_H + ao);
        ldsm4(qlf[ks], sb + Q_L + ao);
    }

    float oacc[8][4];
#pragma unroll
    for (int j = 0; j < 8; j++)
#pragma unroll
        for (int r = 0; r < 4; r++) oacc[j][r] = 0.0f;
    float m_a = -1e30f, m_b = -1e30f, l_a = 0.0f, l_b = 0.0f;

    for (int kt = 0; kt <= qi; kt++) {
        const int st = kt & 1;
        if (kt < qi) load_kv(kt + 1, st ^ 1);

        const uint32_t s0 = sb + STG + st * KV_STAGE;

        float sacc[8][4];
#pragma unroll
        for (int j = 0; j < 8; j++)
#pragma unroll
            for (int r = 0; r < 4; r++) sacc[j][r] = 0.0f;

#pragma unroll
        for (int ks = 0; ks < 4; ks++) {
#pragma unroll
            for (int jp = 0; jp < 4; jp++) {
                uint32_t ro = ((2 * jp + ((lane >> 4) & 1)) * 8 + (lane & 7)) * AP
                            + (ks * 16 + ((lane >> 3) & 1) * 8) * 2;
                uint32_t kbh[4], kbl[4];
                ldsm4(kbh, s0 + 0 * ATILE_B + ro);
                ldsm4(kbl, s0 + 1 * ATILE_B + ro);
                mma16816(sacc[2 * jp],     qhf[ks], &kbh[0]);
                mma16816(sacc[2 * jp],     qlf[ks], &kbh[0]);
                mma16816(sacc[2 * jp],     qhf[ks], &kbl[0]);
                mma16816(sacc[2 * jp + 1], qhf[ks], &kbh[2]);
                mma16816(sacc[2 * jp + 1], qlf[ks], &kbh[2]);
                mma16816(sacc[2 * jp + 1], qhf[ks], &kbl[2]);
            }
        }

        if (kt == qi) {
            const int rA = wq * 16 + (lane >> 2);
            const int rB = rA + 8;
#pragma unroll
            for (int j = 0; j < 8; j++) {
                const int cl = j * 8 + 2 * (lane & 3);
                if (cl     > rA) sacc[j][0] = -1e30f;
                if (cl + 1 > rA) sacc[j][1] = -1e30f;
                if (cl     > rB) sacc[j][2] = -1e30f;
                if (cl + 1 > rB) sacc[j][3] = -1e30f;
            }
        }

        float mx_a = -1e30f, mx_b = -1e30f;
#pragma unroll
        for (int j = 0; j < 8; j++) {
            mx_a = fmaxf(mx_a, fmaxf(sacc[j][0], sacc[j][1]));
            mx_b = fmaxf(mx_b, fmaxf(sacc[j][2], sacc[j][3]));
        }
        mx_a = fmaxf(mx_a, __shfl_xor_sync(0xffffffff, mx_a, 1));
        mx_a = fmaxf(mx_a, __shfl_xor_sync(0xffffffff, mx_a, 2));
        mx_b = fmaxf(mx_b, __shfl_xor_sync(0xffffffff, mx_b, 1));
        mx_b = fmaxf(mx_b, __shfl_xor_sync(0xffffffff, mx_b, 2));

        const float mn_a = fmaxf(m_a, mx_a);
        const float mn_b = fmaxf(m_b, mx_b);
        const float al_a = __expf(m_a - mn_a);
        const float al_b = __expf(m_b - mn_b);
        l_a *= al_a; l_b *= al_b;
        m_a = mn_a;  m_b = mn_b;
#pragma unroll
        for (int j = 0; j < 8; j++) {
            oacc[j][0] *= al_a; oacc[j][1] *= al_a;
            oacc[j][2] *= al_b; oacc[j][3] *= al_b;
        }

        uint32_t pha[8], phb[8], pla[8], plb[8];
#pragma unroll
        for (int j = 0; j < 8; j++) {
            float p0 = __expf(sacc[j][0] - mn_a);
            float p1 = __expf(sacc[j][1] - mn_a);
            float p2 = __expf(sacc[j][2] - mn_b);
            float p3 = __expf(sacc[j][3] - mn_b);
            l_a += p0 + p1;
            l_b += p2 + p3;
            __nv_bfloat16 h0, l0, h1, l1, h2, l2, h3, l3;
            split1(p0, h0, l0); split1(p1, h1, l1);
            split1(p2, h2, l2); split1(p3, h3, l3);
            pha[j] = pack_bf16x2(h0, h1);
            phb[j] = pack_bf16x2(h2, h3);
            pla[j] = pack_bf16x2(l0, l1);
            plb[j] = pack_bf16x2(l2, l3);
        }

#pragma unroll
        for (int ks = 0; ks < 4; ks++) {
            uint32_t Ah[4] = {pha[2 * ks], phb[2 * ks], pha[2 * ks + 1], phb[2 * ks + 1]};
            uint32_t Al[4] = {pla[2 * ks], plb[2 * ks], pla[2 * ks + 1], plb[2 * ks + 1]};
#pragma unroll
            for (int dp = 0; dp < 4; dp++) {
                uint32_t vo = (ks * 16 + (lane & 15)) * AP
                            + (dp * 16 + ((lane >> 4) & 1) * 8) * 2;
                uint32_t vbh[4], vbl[4];
                ldsm4t(vbh, s0 + 2 * ATILE_B + vo);
                ldsm4t(vbl, s0 + 3 * ATILE_B + vo);
                mma16816(oacc[2 * dp],     Ah, &vbh[0]);
                mma16816(oacc[2 * dp],     Al, &vbh[0]);
                mma16816(oacc[2 * dp],     Ah, &vbl[0]);
                mma16816(oacc[2 * dp + 1], Ah, &vbh[2]);
                mma16816(oacc[2 * dp + 1], Al, &vbh[2]);
                mma16816(oacc[2 * dp + 1], Ah, &vbl[2]);
            }
        }

        if (kt < qi) { CP_WAIT(0); }
        __syncthreads();
    }

    l_a += __shfl_xor_sync(0xffffffff, l_a, 1);
    l_a += __shfl_xor_sync(0xffffffff, l_a, 2);
    l_b += __shfl_xor_sync(0xffffffff, l_b, 1);
    l_b += __shfl_xor_sync(0xffffffff, l_b, 2);
    const float inv_a = 1.0f / l_a;
    const float inv_b = 1.0f / l_b;

    const int tA = qi * 64 + wq * 16 + (lane >> 2);
    const int tB = tA + 8;
    const size_t rowA = (size_t)(b * TT + tA) * K3;
    const size_t rowB = (size_t)(b * TT + tB) * K3;
#pragma unroll
    for (int j = 0; j < 8; j++) {
        const int d = h * HD + j * 8 + 2 * (lane & 3);
        float2 vA = make_float2(oacc[j][0] * inv_a, oacc[j][1] * inv_a);
        float2 vB = make_float2(oacc[j][2] * inv_b, oacc[j][3] * inv_b);
        __nv_bfloat16 hA0, lA0, hA1, lA1, hB0, lB0, hB1, lB1;
        split1(vA.x, hA0, lA0); split1(vA.y, hA1, lA1);
        split1(vB.x, hB0, lB0); split1(vB.y, hB1, lB1);
        uint32_t hpA = pack_bf16x2(hA0, hA1), lpA = pack_bf16x2(lA0, lA1);
        uint32_t hpB = pack_bf16x2(hB0, hB1), lpB = pack_bf16x2(lB0, lB1);
        *reinterpret_cast<uint32_t*>(ys + rowA + d)          = hpA;
        *reinterpret_cast<uint32_t*>(ys + rowA + CC + d)     = hpA;
        *reinterpret_cast<uint32_t*>(ys + rowA + 2 * CC + d) = lpA;
        *reinterpret_cast<uint32_t*>(ys + rowB + d)          = hpB;
        *reinterpret_cast<uint32_t*>(ys + rowB + CC + d)     = hpB;
        *reinterpret_cast<uint32_t*>(ys + rowB + 2 * CC + d) = lpB;
    }
}

// ---------------------------------------------------------------------------
extern "C" void kernel_launch(void* const* d_in, const int* in_sizes, int n_in,
                              void* d_out, int out_size)
{
    const float* x     = (const float*)d_in[0];
    const float* w_qkv = (const float*)d_in[1];
    const float* b_qkv = (const float*)d_in[2];
    const float* w_out = (const float*)d_in[3];
    const float* b_out = (const float*)d_in[4];
    float* out = (float*)d_out;

    __nv_bfloat16 *xs, *ys, *wqs, *wos, *qh, *ql, *kh, *kl, *vh, *vl;
    cudaGetSymbolAddress((void**)&xs,  g_xs);
    cudaGetSymbolAddress((void**)&ys,  g_ys);
    cudaGetSymbolAddress((void**)&wqs, g_wqs);
    cudaGetSymbolAddress((void**)&wos, g_wos);
    cudaGetSymbolAddress((void**)&qh,  g_qh);
    cudaGetSymbolAddress((void**)&ql,  g_ql);
    cudaGetSymbolAddress((void**)&kh,  g_kh);
    cudaGetSymbolAddress((void**)&kl,  g_kl);
    cudaGetSymbolAddress((void**)&vh,  g_vh);
    cudaGetSymbolAddress((void**)&vl,  g_vl);

    cudaFuncSetAttribute(gemm_mma<0>, cudaFuncAttributeMaxDynamicSharedMemorySize, GEMM_SMEM);
    cudaFuncSetAttribute(gemm_mma<1>, cudaFuncAttributeMaxDynamicSharedMemorySize, GEMM_SMEM);
    cudaFuncSetAttribute(attn_mma, cudaFuncAttributeMaxDynamicSharedMemorySize, ATTN_SMEM);

    // Input conversions
    {
        int n4 = M_ROWS * CC / 4;
        split3_act<<<(n4 + 255) / 256, 256>>>(x, xs, n4);
        dim3 g1(QKV_N / 32, CC / 32);
        tsplit3<<<g1, 256>>>(w_qkv, QKV_N, wqs);
        dim3 g2(CC / 32, CC / 32);
        tsplit3<<<g2, 256>>>(w_out, CC, wos);
    }

    // 1) QKV GEMM, epilogue writes head-major split q/k/v directly
    {
        dim3 grid(QKV_N / 128, M_ROWS / 128);
        gemm_mma<1><<<grid, 256, GEMM_SMEM>>>(QKV_N, xs, wqs, b_qkv, nullptr,
                                              qh, ql, kh, kl, vh, vl);
    }

    // 2) flash attention -> ys (split3 layout)
    {
        attn_mma<<<BB * HH * NQT, 128, ATTN_SMEM>>>(qh, ql, kh, kl, vh, vl, ys);
    }

    // 3) out = y @ w_out + b_out
    {
        dim3 grid(CC / 128, M_ROWS / 128);
        gemm_mma<0><<<grid, 256, GEMM_SMEM>>>(CC, ys, wos, b_out, out,
                                              nullptr, nullptr, nullptr, nullptr, nullptr, nullptr);
    }
}